// round 1
// baseline (speedup 1.0000x reference)
#include <cuda_runtime.h>
#include <math.h>

#define NROWS 262144
#define TM 32
#define NT 256
#define NTILES (NROWS/TM)
#define GRID 152

// ---- device scratch (no allocation allowed) ----
__device__ float  g_cnorm[1024];
__device__ int    g_counts[1024];
__device__ double g_loss;
__device__ float  g_zq[(size_t)NROWS * 64];

// ---- kernel A shared-memory layout (float offsets) ----
#define A_W1 0                       // 256 x 9 = 2304
#define A_B1 2304                    // 256
#define A_W2 2560                    // 128 rows x 260 (padded from 256) = 33280
#define A_B2 (A_W2 + 128*260)        // 35840, 128
#define A_W3 (A_B2 + 128)            // 35968, 64 rows x 132 (padded from 128) = 8448
#define A_B3 (A_W3 + 64*132)         // 44416, 64
#define A_X  (A_B3 + 64)             // 44480, 32 x 12
#define A_H2 (A_X + 384)             // 44864, 32 x 128
#define A_U  (A_H2 + 4096)           // 48960, 8192 (H1 / ze / cb tile / scratch)
#define A_TOTAL (A_U + 8192)         // 57152 floats = 228608 B

// ---- kernel B shared-memory layout (float offsets) ----
#define B_W1 0                       // 128 rows x 68 (padded from 64) = 8704
#define B_B1 8704                    // 128
#define B_W2 8832                    // 256 rows x 132 (padded from 128) = 33792
#define B_B2 42624                   // 256
#define B_W3 42880                   // 9 rows x 260 (padded from 256) = 2340
#define B_B3 45220                   // 9 (+3 pad)
#define B_D1 45232                   // 32 x 128 = 4096
#define B_D2 49328                   // 32 x 256 = 8192 (also q-tile staging)
#define B_TOTAL 57520                // 230080 B

__device__ __forceinline__ float dot4(float4 a, float4 b, float acc) {
    return fmaf(a.x, b.x, fmaf(a.y, b.y, fmaf(a.z, b.z, fmaf(a.w, b.w, acc))));
}

// ======================= init: cnorm, zero accumulators =======================
__global__ void vq_init_kernel(const float* __restrict__ cb) {
    int j = blockIdx.x * blockDim.x + threadIdx.x;
    if (j < 1024) {
        float sum = 0.f;
        #pragma unroll
        for (int k = 0; k < 64; k += 4) {
            float4 v = *reinterpret_cast<const float4*>(&cb[j*64 + k]);
            sum = dot4(v, v, sum);
        }
        g_cnorm[j]  = sum;
        g_counts[j] = 0;
        if (j == 0) g_loss = 0.0;
    }
}

// ======================= encoder + VQ (argmin, loss, hist) =======================
__global__ void __launch_bounds__(NT, 1) vq_enc_kernel(
    const float* __restrict__ x,
    const float* __restrict__ w1, const float* __restrict__ b1,
    const float* __restrict__ w2, const float* __restrict__ b2,
    const float* __restrict__ w3, const float* __restrict__ b3,
    const float* __restrict__ cb)
{
    extern __shared__ float s[];
    const int tid = threadIdx.x;

    // ---- load all encoder weights into SMEM (padded rows), once per block ----
    for (int i = tid; i < 256*9;   i += NT) s[A_W1 + i] = w1[i];
    for (int i = tid; i < 256;     i += NT) s[A_B1 + i] = b1[i];
    for (int i = tid; i < 128*256; i += NT) { int r = i >> 8, c = i & 255; s[A_W2 + r*260 + c] = w2[i]; }
    for (int i = tid; i < 128;     i += NT) s[A_B2 + i] = b2[i];
    for (int i = tid; i < 64*128;  i += NT) { int r = i >> 7, c = i & 127; s[A_W3 + r*132 + c] = w3[i]; }
    for (int i = tid; i < 64;      i += NT) s[A_B3 + i] = b3[i];
    __syncthreads();

    // layer-1 weights live in registers for the whole block lifetime (c = tid)
    float rw1[9];
    const float rb1 = s[A_B1 + tid];
    #pragma unroll
    for (int k = 0; k < 9; k++) rw1[k] = s[A_W1 + tid*9 + k];

    for (int tile = blockIdx.x; tile < NTILES; tile += gridDim.x) {
        const int row0 = tile * TM;

        // ---- stage x tile [32 x 9] ----
        for (int i = tid; i < TM*9; i += NT) {
            int r = i / 9, c = i - r*9;
            s[A_X + r*12 + c] = x[(size_t)(row0 + r)*9 + c];
        }
        __syncthreads();

        // ---- L1: 9 -> 256, relu. thread owns column c = tid, loops 32 rows ----
        {
            #pragma unroll 4
            for (int r = 0; r < TM; r++) {
                float acc = rb1;
                #pragma unroll
                for (int k = 0; k < 9; k++) acc = fmaf(s[A_X + r*12 + k], rw1[k], acc);
                s[A_U + r*256 + tid] = fmaxf(acc, 0.f);
            }
        }
        __syncthreads();

        // ---- L2: 256 -> 128, relu. c2 = tid&127, 16 rows per thread ----
        {
            const int c2 = tid & 127, rbase = (tid >> 7) * 16;
            float acc[16];
            const float bb = s[A_B2 + c2];
            #pragma unroll
            for (int i = 0; i < 16; i++) acc[i] = bb;
            for (int k = 0; k < 256; k += 4) {
                float4 w = *reinterpret_cast<const float4*>(&s[A_W2 + c2*260 + k]);
                #pragma unroll
                for (int i = 0; i < 16; i++) {
                    float4 h = *reinterpret_cast<const float4*>(&s[A_U + (rbase + i)*256 + k]);
                    acc[i] = dot4(w, h, acc[i]);
                }
            }
            #pragma unroll
            for (int i = 0; i < 16; i++)
                s[A_H2 + (rbase + i)*128 + c2] = fmaxf(acc[i], 0.f);
        }
        __syncthreads();

        // ---- L3: 128 -> 64, linear. writes z_e into A_U[0..2048) ----
        {
            const int c3 = tid & 63, rbase = (tid >> 6) * 8;
            float acc[8];
            const float bb = s[A_B3 + c3];
            #pragma unroll
            for (int i = 0; i < 8; i++) acc[i] = bb;
            for (int k = 0; k < 128; k += 4) {
                float4 w = *reinterpret_cast<const float4*>(&s[A_W3 + c3*132 + k]);
                #pragma unroll
                for (int i = 0; i < 8; i++) {
                    float4 h = *reinterpret_cast<const float4*>(&s[A_H2 + (rbase + i)*128 + k]);
                    acc[i] = dot4(w, h, acc[i]);
                }
            }
            #pragma unroll
            for (int i = 0; i < 8; i++)
                s[A_U + (rbase + i)*64 + c3] = acc[i];
        }
        __syncthreads();

        // ---- distances + running argmin. 8 row-groups x 32 lanes; 2 codes/lane/tile ----
        const int rgd = tid >> 5, cg = tid & 31;
        float best[4]; int bidx[4];
        #pragma unroll
        for (int r = 0; r < 4; r++) { best[r] = 1e30f; bidx[r] = 0; }

        for (int ct = 0; ct < 16; ct++) {
            // stage 64-code tile (padded stride 68) into A_U + 2048
            for (int i = tid; i < 1024; i += NT) {
                int jj = i >> 4, k4 = (i & 15) * 4;
                float4 v = *reinterpret_cast<const float4*>(&cb[(size_t)(ct*64 + jj)*64 + k4]);
                *reinterpret_cast<float4*>(&s[A_U + 2048 + jj*68 + k4]) = v;
            }
            __syncthreads();

            float a0[4] = {0,0,0,0}, a1[4] = {0,0,0,0};
            #pragma unroll 4
            for (int k = 0; k < 64; k += 4) {
                float4 c0 = *reinterpret_cast<const float4*>(&s[A_U + 2048 + cg*68 + k]);
                float4 c1 = *reinterpret_cast<const float4*>(&s[A_U + 2048 + (cg + 32)*68 + k]);
                #pragma unroll
                for (int r = 0; r < 4; r++) {
                    float4 z = *reinterpret_cast<const float4*>(&s[A_U + (rgd*4 + r)*64 + k]);
                    a0[r] = dot4(z, c0, a0[r]);
                    a1[r] = dot4(z, c1, a1[r]);
                }
            }
            const int j0 = ct*64 + cg, j1 = j0 + 32;
            const float cn0 = g_cnorm[j0], cn1 = g_cnorm[j1];
            #pragma unroll
            for (int r = 0; r < 4; r++) {
                float s0 = fmaf(-2.f, a0[r], cn0);
                if (s0 < best[r]) { best[r] = s0; bidx[r] = j0; }
                float s1 = fmaf(-2.f, a1[r], cn1);
                if (s1 < best[r]) { best[r] = s1; bidx[r] = j1; }
            }
            __syncthreads();
        }

        // warp argmin reduce (tie-break: smaller index, matching jnp.argmin)
        #pragma unroll
        for (int off = 16; off; off >>= 1) {
            #pragma unroll
            for (int r = 0; r < 4; r++) {
                float ov = __shfl_down_sync(0xffffffffu, best[r], off);
                int   oi = __shfl_down_sync(0xffffffffu, bidx[r], off);
                if (ov < best[r] || (ov == best[r] && oi < bidx[r])) { best[r] = ov; bidx[r] = oi; }
            }
        }
        int* ridx = (int*)&s[A_U + 2048];
        if (cg == 0) {
            #pragma unroll
            for (int r = 0; r < 4; r++) ridx[rgd*4 + r] = bidx[r];
        }
        __syncthreads();

        // ---- gather quantized, loss partial, histogram, z_q to global ----
        float lloss = 0.f;
        for (int t = tid; t < TM*64; t += NT) {
            int r  = t >> 6;
            int id = ridx[r];
            float q = __ldg(&cb[(size_t)id*64 + (t & 63)]);
            float z = s[A_U + t];
            float d = q - z;
            lloss = fmaf(d, d, lloss);
            g_zq[(size_t)row0*64 + t] = q;
        }
        if (tid < TM) atomicAdd(&g_counts[ridx[tid]], 1);

        #pragma unroll
        for (int off = 16; off; off >>= 1) lloss += __shfl_down_sync(0xffffffffu, lloss, off);
        float* lred = &s[A_U + 2048 + 32];
        if ((tid & 31) == 0) lred[tid >> 5] = lloss;
        __syncthreads();
        if (tid == 0) {
            float tot = 0.f;
            #pragma unroll
            for (int w = 0; w < NT/32; w++) tot += lred[w];
            atomicAdd(&g_loss, (double)tot);
        }
        __syncthreads();
    }
}

// ======================= decoder =======================
__global__ void __launch_bounds__(NT, 1) vq_dec_kernel(
    const float* __restrict__ w1, const float* __restrict__ b1,
    const float* __restrict__ w2, const float* __restrict__ b2,
    const float* __restrict__ w3, const float* __restrict__ b3,
    float* __restrict__ out)
{
    extern __shared__ float s[];
    const int tid = threadIdx.x;

    for (int i = tid; i < 128*64;  i += NT) { int r = i >> 6, c = i & 63;  s[B_W1 + r*68  + c] = w1[i]; }
    for (int i = tid; i < 128;     i += NT) s[B_B1 + i] = b1[i];
    for (int i = tid; i < 256*128; i += NT) { int r = i >> 7, c = i & 127; s[B_W2 + r*132 + c] = w2[i]; }
    for (int i = tid; i < 256;     i += NT) s[B_B2 + i] = b2[i];
    for (int i = tid; i < 9*256;   i += NT) { int r = i / 256, c = i & 255; s[B_W3 + r*260 + c] = w3[i]; }
    for (int i = tid; i < 9;       i += NT) s[B_B3 + i] = b3[i];
    __syncthreads();

    for (int tile = blockIdx.x; tile < NTILES; tile += gridDim.x) {
        const int row0 = tile * TM;

        // stage q tile [32 x 64] into B_D2 region (float4, coalesced)
        for (int t = tid; t < TM*64/4; t += NT) {
            float4 v = *reinterpret_cast<const float4*>(&g_zq[(size_t)row0*64 + t*4]);
            *reinterpret_cast<float4*>(&s[B_D2 + t*4]) = v;
        }
        __syncthreads();

        // ---- D1: 64 -> 128, relu ----
        {
            const int c2 = tid & 127, rbase = (tid >> 7) * 16;
            float acc[16];
            const float bb = s[B_B1 + c2];
            #pragma unroll
            for (int i = 0; i < 16; i++) acc[i] = bb;
            for (int k = 0; k < 64; k += 4) {
                float4 w = *reinterpret_cast<const float4*>(&s[B_W1 + c2*68 + k]);
                #pragma unroll
                for (int i = 0; i < 16; i++) {
                    float4 h = *reinterpret_cast<const float4*>(&s[B_D2 + (rbase + i)*64 + k]);
                    acc[i] = dot4(w, h, acc[i]);
                }
            }
            #pragma unroll
            for (int i = 0; i < 16; i++)
                s[B_D1 + (rbase + i)*128 + c2] = fmaxf(acc[i], 0.f);
        }
        __syncthreads();

        // ---- D2: 128 -> 256, relu. thread owns column c = tid, 32 rows ----
        {
            float acc[32];
            const float bb = s[B_B2 + tid];
            #pragma unroll
            for (int i = 0; i < 32; i++) acc[i] = bb;
            for (int k = 0; k < 128; k += 4) {
                float4 w = *reinterpret_cast<const float4*>(&s[B_W2 + tid*132 + k]);
                #pragma unroll
                for (int i = 0; i < 32; i++) {
                    float4 h = *reinterpret_cast<const float4*>(&s[B_D1 + i*128 + k]);
                    acc[i] = dot4(w, h, acc[i]);
                }
            }
            #pragma unroll
            for (int i = 0; i < 32; i++)
                s[B_D2 + i*256 + tid] = fmaxf(acc[i], 0.f);
        }
        __syncthreads();

        // ---- D3: 256 -> 9, linear, straight to global ----
        for (int t = tid; t < TM*9; t += NT) {
            int r = t / 9, cc = t - r*9;
            float acc = s[B_B3 + cc];
            for (int k = 0; k < 256; k += 4) {
                float4 w = *reinterpret_cast<const float4*>(&s[B_W3 + cc*260 + k]);
                float4 h = *reinterpret_cast<const float4*>(&s[B_D2 + r*256 + k]);
                acc = dot4(w, h, acc);
            }
            out[(size_t)(row0 + r)*9 + cc] = acc;
        }
        __syncthreads();
    }
}

// ======================= finalize scalars =======================
__global__ void vq_final_kernel(float* __restrict__ out) {
    __shared__ double red[NT];
    const int tid = threadIdx.x;
    double ent = 0.0;
    for (int j = tid; j < 1024; j += NT) {
        double p = (double)g_counts[j] / (double)NROWS;
        ent += p * log(p + 1e-10);
    }
    red[tid] = ent;
    __syncthreads();
    for (int off = NT/2; off; off >>= 1) {
        if (tid < off) red[tid] += red[tid + off];
        __syncthreads();
    }
    if (tid == 0) {
        out[(size_t)NROWS*9]     = (float)(g_loss * (1.25 / ((double)NROWS * 64.0)));
        out[(size_t)NROWS*9 + 1] = (float)exp(-red[0]);
    }
}

// ======================= launch =======================
extern "C" void kernel_launch(void* const* d_in, const int* in_sizes, int n_in,
                              void* d_out, int out_size) {
    const float* x   = (const float*)d_in[0];
    const float* ew1 = (const float*)d_in[1];
    const float* eb1 = (const float*)d_in[2];
    const float* ew2 = (const float*)d_in[3];
    const float* eb2 = (const float*)d_in[4];
    const float* ew3 = (const float*)d_in[5];
    const float* eb3 = (const float*)d_in[6];
    const float* dw1 = (const float*)d_in[7];
    const float* db1 = (const float*)d_in[8];
    const float* dw2 = (const float*)d_in[9];
    const float* db2 = (const float*)d_in[10];
    const float* dw3 = (const float*)d_in[11];
    const float* db3 = (const float*)d_in[12];
    const float* cbk = (const float*)d_in[13];
    float* out = (float*)d_out;

    static_assert(A_TOTAL * 4 <= 232448, "enc smem over budget");
    static_assert(B_TOTAL * 4 <= 232448, "dec smem over budget");

    cudaFuncSetAttribute(vq_enc_kernel, cudaFuncAttributeMaxDynamicSharedMemorySize, A_TOTAL * 4);
    cudaFuncSetAttribute(vq_dec_kernel, cudaFuncAttributeMaxDynamicSharedMemorySize, B_TOTAL * 4);

    vq_init_kernel<<<4, 256>>>(cbk);
    vq_enc_kernel<<<GRID, NT, A_TOTAL * 4>>>(x, ew1, eb1, ew2, eb2, ew3, eb3, cbk);
    vq_dec_kernel<<<GRID, NT, B_TOTAL * 4>>>(dw1, db1, dw2, db2, dw3, db3, out);
    vq_final_kernel<<<1, NT>>>(out);
}

// round 2
// speedup vs baseline: 1.0031x; 1.0031x over previous
#include <cuda_runtime.h>
#include <math.h>

#define NROWS 262144
#define TM 32
#define NT 256
#define NTILES (NROWS/TM)
#define GRID 152

// ---- device scratch (no allocation allowed) ----
__device__ float  g_cnorm[1024];
__device__ int    g_counts[1024];
__device__ double g_loss;
__device__ float  g_zq[(size_t)NROWS * 64];

// ---- kernel A shared-memory layout (float offsets) ----
#define A_W1 0                       // 256 x 9 = 2304
#define A_B1 2304                    // 256
#define A_W2 2560                    // 128 rows x 260 (padded from 256) = 33280
#define A_B2 (A_W2 + 128*260)        // 35840, 128
#define A_W3 (A_B2 + 128)            // 35968, 64 rows x 132 (padded from 128) = 8448
#define A_B3 (A_W3 + 64*132)         // 44416, 64
#define A_X  (A_B3 + 64)             // 44480, 32 x 12
#define A_H2 (A_X + 384)             // 44864, 32 x 128
#define A_U  (A_H2 + 4096)           // 48960, 8192 (H1 / ze / cb tile / scratch)
#define A_TOTAL (A_U + 8192)         // 57152 floats = 228608 B

// ---- kernel B shared-memory layout (float offsets) ----
#define B_W1 0                       // 128 rows x 68 (padded from 64) = 8704
#define B_B1 8704                    // 128
#define B_W2 8832                    // 256 rows x 132 (padded from 128) = 33792
#define B_B2 42624                   // 256
#define B_W3 42880                   // 9 rows x 260 (padded from 256) = 2340
#define B_B3 45220                   // 9 (+3 pad)
#define B_D1 45232                   // 32 x 128 = 4096
#define B_D2 49328                   // 32 x 256 = 8192 (also q-tile staging)
#define B_TOTAL 57520                // 230080 B

__device__ __forceinline__ float dot4(float4 a, float4 b, float acc) {
    return fmaf(a.x, b.x, fmaf(a.y, b.y, fmaf(a.z, b.z, fmaf(a.w, b.w, acc))));
}

// ======================= init: cnorm, zero accumulators =======================
__global__ void vq_init_kernel(const float* __restrict__ cb) {
    int j = blockIdx.x * blockDim.x + threadIdx.x;
    if (j < 1024) {
        float sum = 0.f;
        #pragma unroll
        for (int k = 0; k < 64; k += 4) {
            float4 v = *reinterpret_cast<const float4*>(&cb[j*64 + k]);
            sum = dot4(v, v, sum);
        }
        g_cnorm[j]  = sum;
        g_counts[j] = 0;
        if (j == 0) g_loss = 0.0;
    }
}

// ======================= encoder + VQ (argmin, loss, hist) =======================
__global__ void __launch_bounds__(NT, 1) vq_enc_kernel(
    const float* __restrict__ x,
    const float* __restrict__ w1, const float* __restrict__ b1,
    const float* __restrict__ w2, const float* __restrict__ b2,
    const float* __restrict__ w3, const float* __restrict__ b3,
    const float* __restrict__ cb)
{
    extern __shared__ float s[];
    const int tid = threadIdx.x;

    // ---- load all encoder weights into SMEM (padded rows), once per block ----
    for (int i = tid; i < 256*9;   i += NT) s[A_W1 + i] = w1[i];
    for (int i = tid; i < 256;     i += NT) s[A_B1 + i] = b1[i];
    for (int i = tid; i < 128*256; i += NT) { int r = i >> 8, c = i & 255; s[A_W2 + r*260 + c] = w2[i]; }
    for (int i = tid; i < 128;     i += NT) s[A_B2 + i] = b2[i];
    for (int i = tid; i < 64*128;  i += NT) { int r = i >> 7, c = i & 127; s[A_W3 + r*132 + c] = w3[i]; }
    for (int i = tid; i < 64;      i += NT) s[A_B3 + i] = b3[i];
    __syncthreads();

    // layer-1 weights live in registers for the whole block lifetime (c = tid)
    float rw1[9];
    const float rb1 = s[A_B1 + tid];
    #pragma unroll
    for (int k = 0; k < 9; k++) rw1[k] = s[A_W1 + tid*9 + k];

    for (int tile = blockIdx.x; tile < NTILES; tile += gridDim.x) {
        const int row0 = tile * TM;

        // ---- stage x tile [32 x 9] ----
        for (int i = tid; i < TM*9; i += NT) {
            int r = i / 9, c = i - r*9;
            s[A_X + r*12 + c] = x[(size_t)(row0 + r)*9 + c];
        }
        __syncthreads();

        // ---- L1: 9 -> 256, relu. thread owns column c = tid, loops 32 rows ----
        {
            #pragma unroll 4
            for (int r = 0; r < TM; r++) {
                float acc = rb1;
                #pragma unroll
                for (int k = 0; k < 9; k++) acc = fmaf(s[A_X + r*12 + k], rw1[k], acc);
                s[A_U + r*256 + tid] = fmaxf(acc, 0.f);
            }
        }
        __syncthreads();

        // ---- L2: 256 -> 128, relu. c2 = tid&127, 16 rows per thread ----
        {
            const int c2 = tid & 127, rbase = (tid >> 7) * 16;
            float acc[16];
            const float bb = s[A_B2 + c2];
            #pragma unroll
            for (int i = 0; i < 16; i++) acc[i] = bb;
            for (int k = 0; k < 256; k += 4) {
                float4 w = *reinterpret_cast<const float4*>(&s[A_W2 + c2*260 + k]);
                #pragma unroll
                for (int i = 0; i < 16; i++) {
                    float4 h = *reinterpret_cast<const float4*>(&s[A_U + (rbase + i)*256 + k]);
                    acc[i] = dot4(w, h, acc[i]);
                }
            }
            #pragma unroll
            for (int i = 0; i < 16; i++)
                s[A_H2 + (rbase + i)*128 + c2] = fmaxf(acc[i], 0.f);
        }
        __syncthreads();

        // ---- L3: 128 -> 64, linear. writes z_e into A_U[0..2048) ----
        {
            const int c3 = tid & 63, rbase = (tid >> 6) * 8;
            float acc[8];
            const float bb = s[A_B3 + c3];
            #pragma unroll
            for (int i = 0; i < 8; i++) acc[i] = bb;
            for (int k = 0; k < 128; k += 4) {
                float4 w = *reinterpret_cast<const float4*>(&s[A_W3 + c3*132 + k]);
                #pragma unroll
                for (int i = 0; i < 8; i++) {
                    float4 h = *reinterpret_cast<const float4*>(&s[A_H2 + (rbase + i)*128 + k]);
                    acc[i] = dot4(w, h, acc[i]);
                }
            }
            #pragma unroll
            for (int i = 0; i < 8; i++)
                s[A_U + (rbase + i)*64 + c3] = acc[i];
        }
        __syncthreads();

        // ---- distances + running argmin. 8 row-groups x 32 lanes; 2 codes/lane/tile ----
        const int rgd = tid >> 5, cg = tid & 31;
        float best[4]; int bidx[4];
        #pragma unroll
        for (int r = 0; r < 4; r++) { best[r] = 1e30f; bidx[r] = 0; }

        for (int ct = 0; ct < 16; ct++) {
            // stage 64-code tile (padded stride 68) into A_U + 2048
            for (int i = tid; i < 1024; i += NT) {
                int jj = i >> 4, k4 = (i & 15) * 4;
                float4 v = *reinterpret_cast<const float4*>(&cb[(size_t)(ct*64 + jj)*64 + k4]);
                *reinterpret_cast<float4*>(&s[A_U + 2048 + jj*68 + k4]) = v;
            }
            __syncthreads();

            float a0[4] = {0,0,0,0}, a1[4] = {0,0,0,0};
            #pragma unroll 4
            for (int k = 0; k < 64; k += 4) {
                float4 c0 = *reinterpret_cast<const float4*>(&s[A_U + 2048 + cg*68 + k]);
                float4 c1 = *reinterpret_cast<const float4*>(&s[A_U + 2048 + (cg + 32)*68 + k]);
                #pragma unroll
                for (int r = 0; r < 4; r++) {
                    float4 z = *reinterpret_cast<const float4*>(&s[A_U + (rgd*4 + r)*64 + k]);
                    a0[r] = dot4(z, c0, a0[r]);
                    a1[r] = dot4(z, c1, a1[r]);
                }
            }
            const int j0 = ct*64 + cg, j1 = j0 + 32;
            const float cn0 = g_cnorm[j0], cn1 = g_cnorm[j1];
            #pragma unroll
            for (int r = 0; r < 4; r++) {
                float s0 = fmaf(-2.f, a0[r], cn0);
                if (s0 < best[r]) { best[r] = s0; bidx[r] = j0; }
                float s1 = fmaf(-2.f, a1[r], cn1);
                if (s1 < best[r]) { best[r] = s1; bidx[r] = j1; }
            }
            __syncthreads();
        }

        // warp argmin reduce (tie-break: smaller index, matching jnp.argmin)
        #pragma unroll
        for (int off = 16; off; off >>= 1) {
            #pragma unroll
            for (int r = 0; r < 4; r++) {
                float ov = __shfl_down_sync(0xffffffffu, best[r], off);
                int   oi = __shfl_down_sync(0xffffffffu, bidx[r], off);
                if (ov < best[r] || (ov == best[r] && oi < bidx[r])) { best[r] = ov; bidx[r] = oi; }
            }
        }
        int* ridx = (int*)&s[A_U + 2048];
        if (cg == 0) {
            #pragma unroll
            for (int r = 0; r < 4; r++) ridx[rgd*4 + r] = bidx[r];
        }
        __syncthreads();

        // ---- gather quantized, loss partial, histogram, z_q to global ----
        float lloss = 0.f;
        for (int t = tid; t < TM*64; t += NT) {
            int r  = t >> 6;
            int id = ridx[r];
            float q = __ldg(&cb[(size_t)id*64 + (t & 63)]);
            float z = s[A_U + t];
            float d = q - z;
            lloss = fmaf(d, d, lloss);
            g_zq[(size_t)row0*64 + t] = q;
        }
        if (tid < TM) atomicAdd(&g_counts[ridx[tid]], 1);

        #pragma unroll
        for (int off = 16; off; off >>= 1) lloss += __shfl_down_sync(0xffffffffu, lloss, off);
        float* lred = &s[A_U + 2048 + 32];
        if ((tid & 31) == 0) lred[tid >> 5] = lloss;
        __syncthreads();
        if (tid == 0) {
            float tot = 0.f;
            #pragma unroll
            for (int w = 0; w < NT/32; w++) tot += lred[w];
            atomicAdd(&g_loss, (double)tot);
        }
        __syncthreads();
    }
}

// ======================= decoder =======================
__global__ void __launch_bounds__(NT, 1) vq_dec_kernel(
    const float* __restrict__ w1, const float* __restrict__ b1,
    const float* __restrict__ w2, const float* __restrict__ b2,
    const float* __restrict__ w3, const float* __restrict__ b3,
    float* __restrict__ out)
{
    extern __shared__ float s[];
    const int tid = threadIdx.x;

    for (int i = tid; i < 128*64;  i += NT) { int r = i >> 6, c = i & 63;  s[B_W1 + r*68  + c] = w1[i]; }
    for (int i = tid; i < 128;     i += NT) s[B_B1 + i] = b1[i];
    for (int i = tid; i < 256*128; i += NT) { int r = i >> 7, c = i & 127; s[B_W2 + r*132 + c] = w2[i]; }
    for (int i = tid; i < 256;     i += NT) s[B_B2 + i] = b2[i];
    for (int i = tid; i < 9*256;   i += NT) { int r = i / 256, c = i & 255; s[B_W3 + r*260 + c] = w3[i]; }
    for (int i = tid; i < 9;       i += NT) s[B_B3 + i] = b3[i];
    __syncthreads();

    for (int tile = blockIdx.x; tile < NTILES; tile += gridDim.x) {
        const int row0 = tile * TM;

        // stage q tile [32 x 64] into B_D2 region (float4, coalesced)
        for (int t = tid; t < TM*64/4; t += NT) {
            float4 v = *reinterpret_cast<const float4*>(&g_zq[(size_t)row0*64 + t*4]);
            *reinterpret_cast<float4*>(&s[B_D2 + t*4]) = v;
        }
        __syncthreads();

        // ---- D1: 64 -> 128, relu ----
        {
            const int c2 = tid & 127, rbase = (tid >> 7) * 16;
            float acc[16];
            const float bb = s[B_B1 + c2];
            #pragma unroll
            for (int i = 0; i < 16; i++) acc[i] = bb;
            for (int k = 0; k < 64; k += 4) {
                float4 w = *reinterpret_cast<const float4*>(&s[B_W1 + c2*68 + k]);
                #pragma unroll
                for (int i = 0; i < 16; i++) {
                    float4 h = *reinterpret_cast<const float4*>(&s[B_D2 + (rbase + i)*64 + k]);
                    acc[i] = dot4(w, h, acc[i]);
                }
            }
            #pragma unroll
            for (int i = 0; i < 16; i++)
                s[B_D1 + (rbase + i)*128 + c2] = fmaxf(acc[i], 0.f);
        }
        __syncthreads();

        // ---- D2: 128 -> 256, relu. thread owns column c = tid, 32 rows ----
        {
            float acc[32];
            const float bb = s[B_B2 + tid];
            #pragma unroll
            for (int i = 0; i < 32; i++) acc[i] = bb;
            for (int k = 0; k < 128; k += 4) {
                float4 w = *reinterpret_cast<const float4*>(&s[B_W2 + tid*132 + k]);
                #pragma unroll
                for (int i = 0; i < 32; i++) {
                    float4 h = *reinterpret_cast<const float4*>(&s[B_D1 + i*128 + k]);
                    acc[i] = dot4(w, h, acc[i]);
                }
            }
            #pragma unroll
            for (int i = 0; i < 32; i++)
                s[B_D2 + i*256 + tid] = fmaxf(acc[i], 0.f);
        }
        __syncthreads();

        // ---- D3: 256 -> 9, linear, straight to global ----
        for (int t = tid; t < TM*9; t += NT) {
            int r = t / 9, cc = t - r*9;
            float acc = s[B_B3 + cc];
            for (int k = 0; k < 256; k += 4) {
                float4 w = *reinterpret_cast<const float4*>(&s[B_W3 + cc*260 + k]);
                float4 h = *reinterpret_cast<const float4*>(&s[B_D2 + r*256 + k]);
                acc = dot4(w, h, acc);
            }
            out[(size_t)(row0 + r)*9 + cc] = acc;
        }
        __syncthreads();
    }
}

// ======================= finalize scalars =======================
__global__ void vq_final_kernel(float* __restrict__ out) {
    __shared__ double red[NT];
    const int tid = threadIdx.x;
    double ent = 0.0;
    for (int j = tid; j < 1024; j += NT) {
        double p = (double)g_counts[j] / (double)NROWS;
        ent += p * log(p + 1e-10);
    }
    red[tid] = ent;
    __syncthreads();
    for (int off = NT/2; off; off >>= 1) {
        if (tid < off) red[tid] += red[tid + off];
        __syncthreads();
    }
    if (tid == 0) {
        out[(size_t)NROWS*9]     = (float)(g_loss * (1.25 / ((double)NROWS * 64.0)));
        out[(size_t)NROWS*9 + 1] = (float)exp(-red[0]);
    }
}

// ======================= launch =======================
extern "C" void kernel_launch(void* const* d_in, const int* in_sizes, int n_in,
                              void* d_out, int out_size) {
    const float* x   = (const float*)d_in[0];
    const float* ew1 = (const float*)d_in[1];
    const float* eb1 = (const float*)d_in[2];
    const float* ew2 = (const float*)d_in[3];
    const float* eb2 = (const float*)d_in[4];
    const float* ew3 = (const float*)d_in[5];
    const float* eb3 = (const float*)d_in[6];
    const float* dw1 = (const float*)d_in[7];
    const float* db1 = (const float*)d_in[8];
    const float* dw2 = (const float*)d_in[9];
    const float* db2 = (const float*)d_in[10];
    const float* dw3 = (const float*)d_in[11];
    const float* db3 = (const float*)d_in[12];
    const float* cbk = (const float*)d_in[13];
    float* out = (float*)d_out;

    static_assert(A_TOTAL * 4 <= 232448, "enc smem over budget");
    static_assert(B_TOTAL * 4 <= 232448, "dec smem over budget");

    cudaFuncSetAttribute(vq_enc_kernel, cudaFuncAttributeMaxDynamicSharedMemorySize, A_TOTAL * 4);
    cudaFuncSetAttribute(vq_dec_kernel, cudaFuncAttributeMaxDynamicSharedMemorySize, B_TOTAL * 4);

    vq_init_kernel<<<4, 256>>>(cbk);
    vq_enc_kernel<<<GRID, NT, A_TOTAL * 4>>>(x, ew1, eb1, ew2, eb2, ew3, eb3, cbk);
    vq_dec_kernel<<<GRID, NT, B_TOTAL * 4>>>(dw1, db1, dw2, db2, dw3, db3, out);
    vq_final_kernel<<<1, NT>>>(out);
}

// round 3
// speedup vs baseline: 1.3769x; 1.3727x over previous
#include <cuda_runtime.h>
#include <math.h>

typedef unsigned long long ull;

#define NROWS 262144
#define NT 256

// ---------------- device scratch ----------------
__device__ float  g_cnorm[1024];
__device__ int    g_counts[1024];
__device__ double g_loss;
__device__ float  g_ze[(size_t)NROWS * 64];
__device__ int    g_idx[NROWS];

// ---------------- packed f32x2 helpers ----------------
__device__ __forceinline__ void fma2(ull &d, ull a, ull b) {
    asm("fma.rn.f32x2 %0, %1, %2, %0;" : "+l"(d) : "l"(a), "l"(b));
}
__device__ __forceinline__ ull pk2(float lo, float hi) {
    ull r; asm("mov.b64 %0, {%1, %2};" : "=l"(r) : "f"(lo), "f"(hi)); return r;
}
__device__ __forceinline__ float upk_sum(ull v) {
    float lo, hi; asm("mov.b64 {%0, %1}, %2;" : "=f"(lo), "=f"(hi) : "l"(v));
    return lo + hi;
}

// ======================= init =======================
__global__ void vq_init_kernel(const float* __restrict__ cb) {
    int j = blockIdx.x * blockDim.x + threadIdx.x;
    if (j < 1024) {
        float sum = 0.f;
        #pragma unroll
        for (int k = 0; k < 64; k += 4) {
            float4 v = *reinterpret_cast<const float4*>(&cb[j*64 + k]);
            sum = fmaf(v.x,v.x, fmaf(v.y,v.y, fmaf(v.z,v.z, fmaf(v.w,v.w, sum))));
        }
        g_cnorm[j]  = sum;
        g_counts[j] = 0;
        if (j == 0) g_loss = 0.0;
    }
}

// ======================= encoder =======================
#define E_W2 0
#define E_B2 33280
#define E_W3 33408
#define E_B3 41856
#define E_XS 41920
#define E_H1 42240
#define E_H2 50432
#define E_TOTAL 54656

__global__ void __launch_bounds__(NT, 1) vq_enc_kernel(
    const float* __restrict__ x,
    const float* __restrict__ w1, const float* __restrict__ b1,
    const float* __restrict__ w2, const float* __restrict__ b2,
    const float* __restrict__ w3, const float* __restrict__ b3)
{
    extern __shared__ float s[];
    const int tid = threadIdx.x;

    for (int i = tid; i < 128*256; i += NT) { int r = i >> 8, c = i & 255; s[E_W2 + r*260 + c] = w2[i]; }
    for (int i = tid; i < 128;     i += NT) s[E_B2 + i] = b2[i];
    for (int i = tid; i < 64*128;  i += NT) { int r = i >> 7, c = i & 127; s[E_W3 + r*132 + c] = w3[i]; }
    for (int i = tid; i < 64;      i += NT) s[E_B3 + i] = b3[i];

    ull rw1p[9];
    const float rb1 = __ldg(&b1[tid]);
    #pragma unroll
    for (int k = 0; k < 9; k++) { float w = __ldg(&w1[tid*9 + k]); rw1p[k] = pk2(w, w); }
    __syncthreads();

    const int cp  = tid & 63, rg  = tid >> 6;
    const int cq  = tid & 31, rg3 = tid >> 5;

    for (int tile = blockIdx.x; tile < NROWS/32; tile += gridDim.x) {
        const int row0 = tile * 32;

        for (int t = tid; t < 288; t += NT) {
            int r = t / 9, k = t - r*9;
            s[E_XS + k*32 + r] = x[(size_t)(row0 + r)*9 + k];
        }
        __syncthreads();

        // L1: 9 -> 256, relu (col = tid, 16 row-pairs)
        #pragma unroll
        for (int rp = 0; rp < 16; rp++) {
            ull acc = pk2(rb1, rb1);
            #pragma unroll
            for (int k = 0; k < 9; k++)
                fma2(acc, *reinterpret_cast<const ull*>(&s[E_XS + k*32 + 2*rp]), rw1p[k]);
            float lo, hi; asm("mov.b64 {%0,%1}, %2;" : "=f"(lo), "=f"(hi) : "l"(acc));
            s[E_H1 + (2*rp)  *256 + tid] = fmaxf(lo, 0.f);
            s[E_H1 + (2*rp+1)*256 + tid] = fmaxf(hi, 0.f);
        }
        __syncthreads();

        // L2: 256 -> 128, relu (2 cols x 8 rows / thread)
        {
            ull acc[8][2];
            const float bb0 = s[E_B2 + cp], bb1 = s[E_B2 + cp + 64];
            #pragma unroll
            for (int i = 0; i < 8; i++) { acc[i][0] = pk2(bb0, 0.f); acc[i][1] = pk2(bb1, 0.f); }
            const float* w0p = &s[E_W2 + cp*260];
            const float* w1p = &s[E_W2 + (cp+64)*260];
            const float* hp  = &s[E_H1 + rg*8*256];
            #pragma unroll 2
            for (int k4 = 0; k4 < 256; k4 += 4) {
                ulonglong2 w0  = *reinterpret_cast<const ulonglong2*>(w0p + k4);
                ulonglong2 w1v = *reinterpret_cast<const ulonglong2*>(w1p + k4);
                #pragma unroll
                for (int i = 0; i < 8; i++) {
                    ulonglong2 h = *reinterpret_cast<const ulonglong2*>(hp + i*256 + k4);
                    fma2(acc[i][0], w0.x,  h.x); fma2(acc[i][0], w0.y,  h.y);
                    fma2(acc[i][1], w1v.x, h.x); fma2(acc[i][1], w1v.y, h.y);
                }
            }
            #pragma unroll
            for (int i = 0; i < 8; i++) {
                s[E_H2 + (rg*8+i)*132 + cp]      = fmaxf(upk_sum(acc[i][0]), 0.f);
                s[E_H2 + (rg*8+i)*132 + cp + 64] = fmaxf(upk_sum(acc[i][1]), 0.f);
            }
        }
        __syncthreads();

        // L3: 128 -> 64, straight to global z_e
        {
            ull acc[4][2];
            const float bb0 = s[E_B3 + cq], bb1 = s[E_B3 + cq + 32];
            #pragma unroll
            for (int i = 0; i < 4; i++) { acc[i][0] = pk2(bb0, 0.f); acc[i][1] = pk2(bb1, 0.f); }
            const float* w0p = &s[E_W3 + cq*132];
            const float* w1p = &s[E_W3 + (cq+32)*132];
            const float* hp  = &s[E_H2 + rg3*4*132];
            #pragma unroll 2
            for (int k4 = 0; k4 < 128; k4 += 4) {
                ulonglong2 w0  = *reinterpret_cast<const ulonglong2*>(w0p + k4);
                ulonglong2 w1v = *reinterpret_cast<const ulonglong2*>(w1p + k4);
                #pragma unroll
                for (int i = 0; i < 4; i++) {
                    ulonglong2 h = *reinterpret_cast<const ulonglong2*>(hp + i*132 + k4);
                    fma2(acc[i][0], w0.x,  h.x); fma2(acc[i][0], w0.y,  h.y);
                    fma2(acc[i][1], w1v.x, h.x); fma2(acc[i][1], w1v.y, h.y);
                }
            }
            #pragma unroll
            for (int i = 0; i < 4; i++) {
                size_t row = (size_t)(row0 + rg3*4 + i);
                g_ze[row*64 + cq]      = upk_sum(acc[i][0]);
                g_ze[row*64 + cq + 32] = upk_sum(acc[i][1]);
            }
        }
        __syncthreads();
    }
}

// ======================= distance / argmin / loss / hist =======================
#define D_ZS 0
#define D_CB 8704
#define D_SB 17664
#define D_SI 17792
#define D_ZN 17920
#define D_LR 18048
#define D_TOTAL 18056

__global__ void __launch_bounds__(NT, 2) vq_dist_kernel(const float* __restrict__ cb)
{
    extern __shared__ float s[];
    const int tid  = threadIdx.x;
    const int lane = tid & 31, warp = tid >> 5;

    for (int st = blockIdx.x; st < NROWS/128; st += gridDim.x) {
        const size_t base = (size_t)st * 128 * 64;

        for (int i = tid; i < 2048; i += NT) {
            float4 v = *reinterpret_cast<const float4*>(&g_ze[base + (size_t)i*4]);
            int r = i >> 4, c4 = (i & 15) * 4;
            *reinterpret_cast<float4*>(&s[D_ZS + r*68 + c4]) = v;
        }
        __syncthreads();

        if (tid < 128) {
            float zn = 0.f;
            const float* zp = &s[D_ZS + tid*68];
            #pragma unroll
            for (int k = 0; k < 64; k += 4) {
                float4 v = *reinterpret_cast<const float4*>(zp + k);
                zn = fmaf(v.x,v.x, fmaf(v.y,v.y, fmaf(v.z,v.z, fmaf(v.w,v.w, zn))));
            }
            s[D_ZN + tid] = zn;
            s[D_SB + tid] = 1e30f;
            reinterpret_cast<int*>(&s[D_SI])[tid] = 0;
        }
        __syncthreads();

        for (int p = 0; p < 8; p++) {
            const int cbase = p * 128;
            for (int i = tid; i < 2048; i += NT) {
                int r = i >> 4, q4 = (i & 15) * 4;
                ulonglong2 v = *reinterpret_cast<const ulonglong2*>(&cb[(size_t)(cbase + r)*64 + q4]);
                *reinterpret_cast<ull*>(&s[D_CB + r*70 + q4])     = v.x;
                *reinterpret_cast<ull*>(&s[D_CB + r*70 + q4 + 2]) = v.y;
            }
            if (tid < 128) s[D_CB + tid*70 + 64] = g_cnorm[cbase + tid];
            __syncthreads();

            #pragma unroll 1
            for (int rp = 0; rp < 2; rp++) {
                const int r0 = warp*16 + rp*8;
                #pragma unroll 1
                for (int cc = 0; cc < 2; cc++) {
                    const int c0 = cc*64 + lane, c1 = c0 + 32;
                    ull acc0[8], acc1[8];
                    #pragma unroll
                    for (int i = 0; i < 8; i++) { acc0[i] = 0ull; acc1[i] = 0ull; }
                    const float* b0p = &s[D_CB + c0*70];
                    const float* b1p = &s[D_CB + c1*70];
                    const float* ap  = &s[D_ZS + r0*68];
                    #pragma unroll 2
                    for (int k4 = 0; k4 < 64; k4 += 4) {
                        ull b00 = *reinterpret_cast<const ull*>(b0p + k4);
                        ull b01 = *reinterpret_cast<const ull*>(b0p + k4 + 2);
                        ull b10 = *reinterpret_cast<const ull*>(b1p + k4);
                        ull b11 = *reinterpret_cast<const ull*>(b1p + k4 + 2);
                        #pragma unroll
                        for (int i = 0; i < 8; i++) {
                            ulonglong2 a = *reinterpret_cast<const ulonglong2*>(ap + i*68 + k4);
                            fma2(acc0[i], b00, a.x); fma2(acc0[i], b01, a.y);
                            fma2(acc1[i], b10, a.x); fma2(acc1[i], b11, a.y);
                        }
                    }
                    const float cn0 = b0p[64], cn1 = b1p[64];
                    const int j0 = cbase + c0, j1 = cbase + c1;
                    #pragma unroll
                    for (int i = 0; i < 8; i++) {
                        float d0 = fmaf(-2.f, upk_sum(acc0[i]), cn0);
                        float d1 = fmaf(-2.f, upk_sum(acc1[i]), cn1);
                        float v = d0; int id = j0;
                        if (d1 < v) { v = d1; id = j1; }
                        #pragma unroll
                        for (int off = 16; off; off >>= 1) {
                            float ov = __shfl_down_sync(0xffffffffu, v, off);
                            int   oi = __shfl_down_sync(0xffffffffu, id, off);
                            if (ov < v || (ov == v && oi < id)) { v = ov; id = oi; }
                        }
                        if (lane == 0 && v < s[D_SB + r0 + i]) {
                            s[D_SB + r0 + i] = v;
                            reinterpret_cast<int*>(&s[D_SI])[r0 + i] = id;
                        }
                    }
                }
            }
            __syncthreads();
        }

        float ll = 0.f;
        if (tid < 128) {
            int id = reinterpret_cast<int*>(&s[D_SI])[tid];
            ll = s[D_SB + tid] + s[D_ZN + tid];
            g_idx[st*128 + tid] = id;
            atomicAdd(&g_counts[id], 1);
        }
        #pragma unroll
        for (int off = 16; off; off >>= 1) ll += __shfl_down_sync(0xffffffffu, ll, off);
        if (lane == 0) s[D_LR + warp] = ll;
        __syncthreads();
        if (tid == 0) {
            float tot = 0.f;
            #pragma unroll
            for (int w = 0; w < 8; w++) tot += s[D_LR + w];
            atomicAdd(&g_loss, (double)tot);
        }
        __syncthreads();
    }
}

// ======================= decoder =======================
#define C_W1  0
#define C_B1  8704
#define C_W2  8832
#define C_B2  42624
#define C_W3  42880
#define C_B3  45220
#define C_S1  45232
#define C_S2  53552
#define C_IDX 57776
#define C_TOTAL 57808

__global__ void __launch_bounds__(NT, 1) vq_dec_kernel(
    const float* __restrict__ w1, const float* __restrict__ b1,
    const float* __restrict__ w2, const float* __restrict__ b2,
    const float* __restrict__ w3, const float* __restrict__ b3,
    const float* __restrict__ cb, float* __restrict__ out)
{
    extern __shared__ float s[];
    const int tid = threadIdx.x;

    for (int i = tid; i < 128*64;  i += NT) { int r = i >> 6, c = i & 63;  s[C_W1 + r*68  + c] = w1[i]; }
    for (int i = tid; i < 128;     i += NT) s[C_B1 + i] = b1[i];
    for (int i = tid; i < 256*128; i += NT) { int r = i >> 7, c = i & 127; s[C_W2 + r*132 + c] = w2[i]; }
    for (int i = tid; i < 256;     i += NT) s[C_B2 + i] = b2[i];
    for (int i = tid; i < 9*256;   i += NT) { int r = i >> 8, c = i & 255; s[C_W3 + r*260 + c] = w3[i]; }
    for (int i = tid; i < 9;       i += NT) s[C_B3 + i] = b3[i];
    __syncthreads();

    const int cp  = tid & 63,  rg  = tid >> 6;
    const int cq  = tid & 127, rg2 = tid >> 7;
    int* sidx = reinterpret_cast<int*>(&s[C_IDX]);

    for (int tile = blockIdx.x; tile < NROWS/32; tile += gridDim.x) {
        const int row0 = tile * 32;
        if (tid < 32) sidx[tid] = g_idx[row0 + tid];
        __syncthreads();

        // gather quantized rows from codebook (L2-resident)
        {
            int r = tid >> 3, j = (tid & 7) * 8;
            const float* src = &cb[(size_t)sidx[r]*64 + j];
            float4 v0 = *reinterpret_cast<const float4*>(src);
            float4 v1 = *reinterpret_cast<const float4*>(src + 4);
            *reinterpret_cast<float4*>(&s[C_S1 + r*68 + j])     = v0;
            *reinterpret_cast<float4*>(&s[C_S1 + r*68 + j + 4]) = v1;
        }
        __syncthreads();

        // D1: 64 -> 128, relu
        {
            ull acc[8][2];
            const float bb0 = s[C_B1 + cp], bb1 = s[C_B1 + cp + 64];
            #pragma unroll
            for (int i = 0; i < 8; i++) { acc[i][0] = pk2(bb0, 0.f); acc[i][1] = pk2(bb1, 0.f); }
            const float* w0p = &s[C_W1 + cp*68];
            const float* w1p = &s[C_W1 + (cp+64)*68];
            const float* hp  = &s[C_S1 + rg*8*68];
            #pragma unroll 2
            for (int k4 = 0; k4 < 64; k4 += 4) {
                ulonglong2 w0  = *reinterpret_cast<const ulonglong2*>(w0p + k4);
                ulonglong2 w1v = *reinterpret_cast<const ulonglong2*>(w1p + k4);
                #pragma unroll
                for (int i = 0; i < 8; i++) {
                    ulonglong2 h = *reinterpret_cast<const ulonglong2*>(hp + i*68 + k4);
                    fma2(acc[i][0], w0.x,  h.x); fma2(acc[i][0], w0.y,  h.y);
                    fma2(acc[i][1], w1v.x, h.x); fma2(acc[i][1], w1v.y, h.y);
                }
            }
            #pragma unroll
            for (int i = 0; i < 8; i++) {
                s[C_S2 + (rg*8+i)*132 + cp]      = fmaxf(upk_sum(acc[i][0]), 0.f);
                s[C_S2 + (rg*8+i)*132 + cp + 64] = fmaxf(upk_sum(acc[i][1]), 0.f);
            }
        }
        __syncthreads();

        // D2: 128 -> 256, relu
        {
            ull acc[16][2];
            const float bb0 = s[C_B2 + cq], bb1 = s[C_B2 + cq + 128];
            #pragma unroll
            for (int i = 0; i < 16; i++) { acc[i][0] = pk2(bb0, 0.f); acc[i][1] = pk2(bb1, 0.f); }
            const float* w0p = &s[C_W2 + cq*132];
            const float* w1p = &s[C_W2 + (cq+128)*132];
            const float* hp  = &s[C_S2 + rg2*16*132];
            #pragma unroll 2
            for (int k4 = 0; k4 < 128; k4 += 4) {
                ulonglong2 w0  = *reinterpret_cast<const ulonglong2*>(w0p + k4);
                ulonglong2 w1v = *reinterpret_cast<const ulonglong2*>(w1p + k4);
                #pragma unroll
                for (int i = 0; i < 16; i++) {
                    ulonglong2 h = *reinterpret_cast<const ulonglong2*>(hp + i*132 + k4);
                    fma2(acc[i][0], w0.x,  h.x); fma2(acc[i][0], w0.y,  h.y);
                    fma2(acc[i][1], w1v.x, h.x); fma2(acc[i][1], w1v.y, h.y);
                }
            }
            #pragma unroll
            for (int i = 0; i < 16; i++) {
                s[C_S1 + (rg2*16+i)*260 + cq]       = fmaxf(upk_sum(acc[i][0]), 0.f);
                s[C_S1 + (rg2*16+i)*260 + cq + 128] = fmaxf(upk_sum(acc[i][1]), 0.f);
            }
        }
        __syncthreads();

        // D3: 256 -> 9
        for (int t = tid; t < 288; t += NT) {
            int r = t / 9, c = t - r*9;
            ull a0 = pk2(s[C_B3 + c], 0.f), a1 = 0ull;
            const float* wp  = &s[C_W3 + c*260];
            const float* hp2 = &s[C_S1 + r*260];
            #pragma unroll 4
            for (int k4 = 0; k4 < 256; k4 += 4) {
                ulonglong2 w = *reinterpret_cast<const ulonglong2*>(wp + k4);
                ulonglong2 h = *reinterpret_cast<const ulonglong2*>(hp2 + k4);
                fma2(a0, w.x, h.x); fma2(a1, w.y, h.y);
            }
            out[(size_t)(row0 + r)*9 + c] = upk_sum(a0) + upk_sum(a1);
        }
        __syncthreads();
    }
}

// ======================= finalize =======================
__global__ void vq_final_kernel(float* __restrict__ out) {
    __shared__ double red[NT];
    const int tid = threadIdx.x;
    double ent = 0.0;
    for (int j = tid; j < 1024; j += NT) {
        double p = (double)g_counts[j] / (double)NROWS;
        ent += p * log(p + 1e-10);
    }
    red[tid] = ent;
    __syncthreads();
    for (int off = NT/2; off; off >>= 1) {
        if (tid < off) red[tid] += red[tid + off];
        __syncthreads();
    }
    if (tid == 0) {
        out[(size_t)NROWS*9]     = (float)(g_loss * (1.25 / ((double)NROWS * 64.0)));
        out[(size_t)NROWS*9 + 1] = (float)exp(-red[0]);
    }
}

// ======================= launch =======================
extern "C" void kernel_launch(void* const* d_in, const int* in_sizes, int n_in,
                              void* d_out, int out_size) {
    const float* x   = (const float*)d_in[0];
    const float* ew1 = (const float*)d_in[1];
    const float* eb1 = (const float*)d_in[2];
    const float* ew2 = (const float*)d_in[3];
    const float* eb2 = (const float*)d_in[4];
    const float* ew3 = (const float*)d_in[5];
    const float* eb3 = (const float*)d_in[6];
    const float* dw1 = (const float*)d_in[7];
    const float* db1 = (const float*)d_in[8];
    const float* dw2 = (const float*)d_in[9];
    const float* db2 = (const float*)d_in[10];
    const float* dw3 = (const float*)d_in[11];
    const float* db3 = (const float*)d_in[12];
    const float* cbk = (const float*)d_in[13];
    float* out = (float*)d_out;

    static_assert(E_TOTAL * 4 <= 232448, "enc smem");
    static_assert(D_TOTAL * 4 <= 116224, "dist smem x2");
    static_assert(C_TOTAL * 4 <= 232448, "dec smem");

    cudaFuncSetAttribute(vq_enc_kernel,  cudaFuncAttributeMaxDynamicSharedMemorySize, E_TOTAL * 4);
    cudaFuncSetAttribute(vq_dist_kernel, cudaFuncAttributeMaxDynamicSharedMemorySize, D_TOTAL * 4);
    cudaFuncSetAttribute(vq_dec_kernel,  cudaFuncAttributeMaxDynamicSharedMemorySize, C_TOTAL * 4);

    vq_init_kernel<<<4, 256>>>(cbk);
    vq_enc_kernel<<<152, NT, E_TOTAL * 4>>>(x, ew1, eb1, ew2, eb2, ew3, eb3);
    vq_dist_kernel<<<304, NT, D_TOTAL * 4>>>(cbk);
    vq_dec_kernel<<<152, NT, C_TOTAL * 4>>>(dw1, db1, dw2, db2, dw3, db3, cbk, out);
    vq_final_kernel<<<1, NT>>>(out);
}

// round 5
// speedup vs baseline: 1.4210x; 1.0320x over previous
#include <cuda_runtime.h>
#include <math.h>

typedef unsigned long long ull;

#define NROWS 262144

// ---------------- device scratch ----------------
__device__ float  g_cnorm[1024];
__device__ int    g_counts[1024];
__device__ double g_loss;
__device__ float  g_ze[(size_t)NROWS * 64];
__device__ int    g_idx[NROWS];

// ---------------- packed f32x2 helpers ----------------
__device__ __forceinline__ void fma2(ull &d, ull a, ull b) {
    asm("fma.rn.f32x2 %0, %1, %2, %0;" : "+l"(d) : "l"(a), "l"(b));
}
__device__ __forceinline__ ull pk2(float lo, float hi) {
    ull r; asm("mov.b64 %0, {%1, %2};" : "=l"(r) : "f"(lo), "f"(hi)); return r;
}
__device__ __forceinline__ float upk_sum(ull v) {
    float lo, hi; asm("mov.b64 {%0, %1}, %2;" : "=f"(lo), "=f"(hi) : "l"(v));
    return lo + hi;
}

// ======================= init =======================
__global__ void vq_init_kernel(const float* __restrict__ cb) {
    int j = blockIdx.x * blockDim.x + threadIdx.x;
    if (j < 1024) {
        float sum = 0.f;
        #pragma unroll
        for (int k = 0; k < 64; k += 4) {
            float4 v = *reinterpret_cast<const float4*>(&cb[j*64 + k]);
            sum = fmaf(v.x,v.x, fmaf(v.y,v.y, fmaf(v.z,v.z, fmaf(v.w,v.w, sum))));
        }
        g_cnorm[j]  = sum;
        g_counts[j] = 0;
        if (j == 0) g_loss = 0.0;
    }
}

// ======================= encoder (512 threads) =======================
#define E_W2 0
#define E_B2 33280
#define E_W3 33408
#define E_B3 41856
#define E_XS 41920
#define E_H1 42240
#define E_H2 50432
#define E_TOTAL 54656
#define ENT 512

__global__ void __launch_bounds__(ENT, 1) vq_enc_kernel(
    const float* __restrict__ x,
    const float* __restrict__ w1, const float* __restrict__ b1,
    const float* __restrict__ w2, const float* __restrict__ b2,
    const float* __restrict__ w3, const float* __restrict__ b3)
{
    extern __shared__ float s[];
    const int tid = threadIdx.x;

    for (int i = tid; i < 128*256; i += ENT) { int r = i >> 8, c = i & 255; s[E_W2 + r*260 + c] = w2[i]; }
    for (int i = tid; i < 128;     i += ENT) s[E_B2 + i] = b2[i];
    for (int i = tid; i < 64*128;  i += ENT) { int r = i >> 7, c = i & 127; s[E_W3 + r*132 + c] = w3[i]; }
    for (int i = tid; i < 64;      i += ENT) s[E_B3 + i] = b3[i];

    const int col1 = tid & 255;               // L1 column
    const int rp0  = (tid >> 8) * 8;          // L1: 8 row-pairs per thread
    ull rw1p[9];
    const float rb1 = __ldg(&b1[col1]);
    #pragma unroll
    for (int k = 0; k < 9; k++) { float w = __ldg(&w1[col1*9 + k]); rw1p[k] = pk2(w, w); }
    __syncthreads();

    const int cp  = tid & 63, rg  = tid >> 6;   // L2: cols (cp, cp+64),  rows rg*4..+3
    const int cq  = tid & 31, rg3 = tid >> 5;   // L3: cols (cq, cq+32),  rows rg3*2..+1

    for (int tile = blockIdx.x; tile < NROWS/32; tile += gridDim.x) {
        const int row0 = tile * 32;

        if (tid < 288) {
            int r = tid / 9, k = tid - r*9;
            s[E_XS + k*32 + r] = x[(size_t)(row0 + r)*9 + k];
        }
        __syncthreads();

        // L1: 9 -> 256, relu (8 row-pairs per thread)
        #pragma unroll
        for (int j = 0; j < 8; j++) {
            const int rp = rp0 + j;
            ull acc = pk2(rb1, rb1);
            #pragma unroll
            for (int k = 0; k < 9; k++)
                fma2(acc, *reinterpret_cast<const ull*>(&s[E_XS + k*32 + 2*rp]), rw1p[k]);
            float lo, hi; asm("mov.b64 {%0,%1}, %2;" : "=f"(lo), "=f"(hi) : "l"(acc));
            s[E_H1 + (2*rp)  *256 + col1] = fmaxf(lo, 0.f);
            s[E_H1 + (2*rp+1)*256 + col1] = fmaxf(hi, 0.f);
        }
        __syncthreads();

        // L2: 256 -> 128, relu (2 cols x 4 rows)
        {
            ull acc[4][2];
            const float bb0 = s[E_B2 + cp], bb1 = s[E_B2 + cp + 64];
            #pragma unroll
            for (int i = 0; i < 4; i++) { acc[i][0] = pk2(bb0, 0.f); acc[i][1] = pk2(bb1, 0.f); }
            const float* w0p = &s[E_W2 + cp*260];
            const float* w1p = &s[E_W2 + (cp+64)*260];
            const float* hp  = &s[E_H1 + rg*4*256];
            #pragma unroll 4
            for (int k4 = 0; k4 < 256; k4 += 4) {
                ulonglong2 w0  = *reinterpret_cast<const ulonglong2*>(w0p + k4);
                ulonglong2 w1v = *reinterpret_cast<const ulonglong2*>(w1p + k4);
                #pragma unroll
                for (int i = 0; i < 4; i++) {
                    ulonglong2 h = *reinterpret_cast<const ulonglong2*>(hp + i*256 + k4);
                    fma2(acc[i][0], w0.x,  h.x); fma2(acc[i][0], w0.y,  h.y);
                    fma2(acc[i][1], w1v.x, h.x); fma2(acc[i][1], w1v.y, h.y);
                }
            }
            #pragma unroll
            for (int i = 0; i < 4; i++) {
                s[E_H2 + (rg*4+i)*132 + cp]      = fmaxf(upk_sum(acc[i][0]), 0.f);
                s[E_H2 + (rg*4+i)*132 + cp + 64] = fmaxf(upk_sum(acc[i][1]), 0.f);
            }
        }
        __syncthreads();

        // L3: 128 -> 64, straight to global z_e (2 cols x 2 rows)
        {
            ull acc[2][2];
            const float bb0 = s[E_B3 + cq], bb1 = s[E_B3 + cq + 32];
            #pragma unroll
            for (int i = 0; i < 2; i++) { acc[i][0] = pk2(bb0, 0.f); acc[i][1] = pk2(bb1, 0.f); }
            const float* w0p = &s[E_W3 + cq*132];
            const float* w1p = &s[E_W3 + (cq+32)*132];
            const float* hp  = &s[E_H2 + rg3*2*132];
            #pragma unroll 4
            for (int k4 = 0; k4 < 128; k4 += 4) {
                ulonglong2 w0  = *reinterpret_cast<const ulonglong2*>(w0p + k4);
                ulonglong2 w1v = *reinterpret_cast<const ulonglong2*>(w1p + k4);
                #pragma unroll
                for (int i = 0; i < 2; i++) {
                    ulonglong2 h = *reinterpret_cast<const ulonglong2*>(hp + i*132 + k4);
                    fma2(acc[i][0], w0.x,  h.x); fma2(acc[i][0], w0.y,  h.y);
                    fma2(acc[i][1], w1v.x, h.x); fma2(acc[i][1], w1v.y, h.y);
                }
            }
            #pragma unroll
            for (int i = 0; i < 2; i++) {
                size_t row = (size_t)(row0 + rg3*2 + i);
                g_ze[row*64 + cq]      = upk_sum(acc[i][0]);
                g_ze[row*64 + cq + 32] = upk_sum(acc[i][1]);
            }
        }
        __syncthreads();
    }
}

// ======================= distance / argmin / loss / hist =======================
#define D_ZS 0
#define D_CB 8704
#define D_SB 17664
#define D_SI 17792
#define D_ZN 17920
#define D_LR 18048
#define D_TOTAL 18056
#define DNT 256

__global__ void __launch_bounds__(DNT, 2) vq_dist_kernel(const float* __restrict__ cb)
{
    extern __shared__ float s[];
    const int tid  = threadIdx.x;
    const int lane = tid & 31, warp = tid >> 5;
    const int r0 = warp * 16;                  // each warp owns 16 rows of the 128-row tile

    for (int st = blockIdx.x; st < NROWS/128; st += gridDim.x) {
        const size_t base = (size_t)st * 128 * 64;

        for (int i = tid; i < 2048; i += DNT) {
            float4 v = *reinterpret_cast<const float4*>(&g_ze[base + (size_t)i*4]);
            int r = i >> 4, c4 = (i & 15) * 4;
            *reinterpret_cast<float4*>(&s[D_ZS + r*68 + c4]) = v;
        }
        __syncthreads();

        if (tid < 128) {
            float zn = 0.f;
            const float* zp = &s[D_ZS + tid*68];
            #pragma unroll
            for (int k = 0; k < 64; k += 4) {
                float4 v = *reinterpret_cast<const float4*>(zp + k);
                zn = fmaf(v.x,v.x, fmaf(v.y,v.y, fmaf(v.z,v.z, fmaf(v.w,v.w, zn))));
            }
            s[D_ZN + tid] = zn;
            s[D_SB + tid] = 1e30f;
            reinterpret_cast<int*>(&s[D_SI])[tid] = 0;
        }
        __syncthreads();

        for (int p = 0; p < 8; p++) {
            const int cbase = p * 128;
            for (int i = tid; i < 2048; i += DNT) {
                int r = i >> 4, q4 = (i & 15) * 4;
                ulonglong2 v = *reinterpret_cast<const ulonglong2*>(&cb[(size_t)(cbase + r)*64 + q4]);
                *reinterpret_cast<ull*>(&s[D_CB + r*70 + q4])     = v.x;
                *reinterpret_cast<ull*>(&s[D_CB + r*70 + q4 + 2]) = v.y;
            }
            if (tid < 128) s[D_CB + tid*70 + 64] = g_cnorm[cbase + tid];
            __syncthreads();

            #pragma unroll 1
            for (int cc = 0; cc < 2; cc++) {
                const int c0 = cc*64 + lane, c1 = c0 + 32;
                ull acc0[16], acc1[16];
                #pragma unroll
                for (int i = 0; i < 16; i++) { acc0[i] = 0ull; acc1[i] = 0ull; }
                const float* b0p = &s[D_CB + c0*70];
                const float* b1p = &s[D_CB + c1*70];
                const float* ap  = &s[D_ZS + r0*68];
                #pragma unroll 2
                for (int k4 = 0; k4 < 64; k4 += 4) {
                    // stride-70 rows are only 8B-aligned: must stay ull (8B) loads
                    ull b00 = *reinterpret_cast<const ull*>(b0p + k4);
                    ull b01 = *reinterpret_cast<const ull*>(b0p + k4 + 2);
                    ull b10 = *reinterpret_cast<const ull*>(b1p + k4);
                    ull b11 = *reinterpret_cast<const ull*>(b1p + k4 + 2);
                    #pragma unroll
                    for (int i = 0; i < 16; i++) {
                        ulonglong2 a = *reinterpret_cast<const ulonglong2*>(ap + i*68 + k4);
                        fma2(acc0[i], b00, a.x); fma2(acc0[i], b01, a.y);
                        fma2(acc1[i], b10, a.x); fma2(acc1[i], b11, a.y);
                    }
                }
                const float cn0 = b0p[64], cn1 = b1p[64];
                const int j0 = cbase + c0, j1 = cbase + c1;
                #pragma unroll
                for (int i = 0; i < 16; i++) {
                    float d0 = fmaf(-2.f, upk_sum(acc0[i]), cn0);
                    float d1 = fmaf(-2.f, upk_sum(acc1[i]), cn1);
                    float v = d0; int id = j0;
                    if (d1 < v) { v = d1; id = j1; }
                    #pragma unroll
                    for (int off = 16; off; off >>= 1) {
                        float ov = __shfl_down_sync(0xffffffffu, v, off);
                        int   oi = __shfl_down_sync(0xffffffffu, id, off);
                        if (ov < v || (ov == v && oi < id)) { v = ov; id = oi; }
                    }
                    if (lane == 0 && v < s[D_SB + r0 + i]) {
                        s[D_SB + r0 + i] = v;
                        reinterpret_cast<int*>(&s[D_SI])[r0 + i] = id;
                    }
                }
            }
            __syncthreads();
        }

        float ll = 0.f;
        if (tid < 128) {
            int id = reinterpret_cast<int*>(&s[D_SI])[tid];
            ll = s[D_SB + tid] + s[D_ZN + tid];
            g_idx[st*128 + tid] = id;
            atomicAdd(&g_counts[id], 1);
        }
        #pragma unroll
        for (int off = 16; off; off >>= 1) ll += __shfl_down_sync(0xffffffffu, ll, off);
        if (lane == 0) s[D_LR + warp] = ll;
        __syncthreads();
        if (tid == 0) {
            float tot = 0.f;
            #pragma unroll
            for (int w = 0; w < 8; w++) tot += s[D_LR + w];
            atomicAdd(&g_loss, (double)tot);
        }
        __syncthreads();
    }
}

// ======================= decoder (512 threads) =======================
#define C_W1  0
#define C_B1  8704
#define C_W2  8832
#define C_B2  42624
#define C_W3  42880
#define C_B3  45220
#define C_S1  45232
#define C_S2  53552
#define C_IDX 57776
#define C_TOTAL 57808
#define CNT 512

__global__ void __launch_bounds__(CNT, 1) vq_dec_kernel(
    const float* __restrict__ w1, const float* __restrict__ b1,
    const float* __restrict__ w2, const float* __restrict__ b2,
    const float* __restrict__ w3, const float* __restrict__ b3,
    const float* __restrict__ cb, float* __restrict__ out)
{
    extern __shared__ float s[];
    const int tid = threadIdx.x;

    for (int i = tid; i < 128*64;  i += CNT) { int r = i >> 6, c = i & 63;  s[C_W1 + r*68  + c] = w1[i]; }
    for (int i = tid; i < 128;     i += CNT) s[C_B1 + i] = b1[i];
    for (int i = tid; i < 256*128; i += CNT) { int r = i >> 7, c = i & 127; s[C_W2 + r*132 + c] = w2[i]; }
    for (int i = tid; i < 256;     i += CNT) s[C_B2 + i] = b2[i];
    for (int i = tid; i < 9*256;   i += CNT) { int r = i >> 8, c = i & 255; s[C_W3 + r*260 + c] = w3[i]; }
    for (int i = tid; i < 9;       i += CNT) s[C_B3 + i] = b3[i];
    __syncthreads();

    const int cp  = tid & 63,  rg  = tid >> 6;   // D1: cols (cp, cp+64),  rows rg*4..+3
    const int cq  = tid & 127, rg2 = tid >> 7;   // D2: cols (cq, cq+128), rows rg2*8..+7
    int* sidx = reinterpret_cast<int*>(&s[C_IDX]);

    for (int tile = blockIdx.x; tile < NROWS/32; tile += gridDim.x) {
        const int row0 = tile * 32;
        if (tid < 32) sidx[tid] = g_idx[row0 + tid];
        __syncthreads();

        // gather quantized rows from codebook (L2-resident): 1 float4 per thread
        {
            int r = tid >> 4, j = (tid & 15) * 4;
            float4 v = *reinterpret_cast<const float4*>(&cb[(size_t)sidx[r]*64 + j]);
            *reinterpret_cast<float4*>(&s[C_S1 + r*68 + j]) = v;
        }
        __syncthreads();

        // D1: 64 -> 128, relu (2 cols x 4 rows)
        {
            ull acc[4][2];
            const float bb0 = s[C_B1 + cp], bb1 = s[C_B1 + cp + 64];
            #pragma unroll
            for (int i = 0; i < 4; i++) { acc[i][0] = pk2(bb0, 0.f); acc[i][1] = pk2(bb1, 0.f); }
            const float* w0p = &s[C_W1 + cp*68];
            const float* w1p = &s[C_W1 + (cp+64)*68];
            const float* hp  = &s[C_S1 + rg*4*68];
            #pragma unroll 4
            for (int k4 = 0; k4 < 64; k4 += 4) {
                ulonglong2 w0  = *reinterpret_cast<const ulonglong2*>(w0p + k4);
                ulonglong2 w1v = *reinterpret_cast<const ulonglong2*>(w1p + k4);
                #pragma unroll
                for (int i = 0; i < 4; i++) {
                    ulonglong2 h = *reinterpret_cast<const ulonglong2*>(hp + i*68 + k4);
                    fma2(acc[i][0], w0.x,  h.x); fma2(acc[i][0], w0.y,  h.y);
                    fma2(acc[i][1], w1v.x, h.x); fma2(acc[i][1], w1v.y, h.y);
                }
            }
            #pragma unroll
            for (int i = 0; i < 4; i++) {
                s[C_S2 + (rg*4+i)*132 + cp]      = fmaxf(upk_sum(acc[i][0]), 0.f);
                s[C_S2 + (rg*4+i)*132 + cp + 64] = fmaxf(upk_sum(acc[i][1]), 0.f);
            }
        }
        __syncthreads();

        // D2: 128 -> 256, relu (2 cols x 8 rows)
        {
            ull acc[8][2];
            const float bb0 = s[C_B2 + cq], bb1 = s[C_B2 + cq + 128];
            #pragma unroll
            for (int i = 0; i < 8; i++) { acc[i][0] = pk2(bb0, 0.f); acc[i][1] = pk2(bb1, 0.f); }
            const float* w0p = &s[C_W2 + cq*132];
            const float* w1p = &s[C_W2 + (cq+128)*132];
            const float* hp  = &s[C_S2 + rg2*8*132];
            #pragma unroll 4
            for (int k4 = 0; k4 < 128; k4 += 4) {
                ulonglong2 w0  = *reinterpret_cast<const ulonglong2*>(w0p + k4);
                ulonglong2 w1v = *reinterpret_cast<const ulonglong2*>(w1p + k4);
                #pragma unroll
                for (int i = 0; i < 8; i++) {
                    ulonglong2 h = *reinterpret_cast<const ulonglong2*>(hp + i*132 + k4);
                    fma2(acc[i][0], w0.x,  h.x); fma2(acc[i][0], w0.y,  h.y);
                    fma2(acc[i][1], w1v.x, h.x); fma2(acc[i][1], w1v.y, h.y);
                }
            }
            #pragma unroll
            for (int i = 0; i < 8; i++) {
                s[C_S1 + (rg2*8+i)*260 + cq]       = fmaxf(upk_sum(acc[i][0]), 0.f);
                s[C_S1 + (rg2*8+i)*260 + cq + 128] = fmaxf(upk_sum(acc[i][1]), 0.f);
            }
        }
        __syncthreads();

        // D3: 256 -> 9
        if (tid < 288) {
            int r = tid / 9, c = tid - r*9;
            ull a0 = pk2(s[C_B3 + c], 0.f), a1 = 0ull;
            const float* wp  = &s[C_W3 + c*260];
            const float* hp2 = &s[C_S1 + r*260];
            #pragma unroll 4
            for (int k4 = 0; k4 < 256; k4 += 4) {
                ulonglong2 w = *reinterpret_cast<const ulonglong2*>(wp + k4);
                ulonglong2 h = *reinterpret_cast<const ulonglong2*>(hp2 + k4);
                fma2(a0, w.x, h.x); fma2(a1, w.y, h.y);
            }
            out[(size_t)(row0 + r)*9 + c] = upk_sum(a0) + upk_sum(a1);
        }
        __syncthreads();
    }
}

// ======================= finalize =======================
__global__ void vq_final_kernel(float* __restrict__ out) {
    __shared__ double red[256];
    const int tid = threadIdx.x;
    double ent = 0.0;
    for (int j = tid; j < 1024; j += 256) {
        double p = (double)g_counts[j] / (double)NROWS;
        ent += p * log(p + 1e-10);
    }
    red[tid] = ent;
    __syncthreads();
    for (int off = 128; off; off >>= 1) {
        if (tid < off) red[tid] += red[tid + off];
        __syncthreads();
    }
    if (tid == 0) {
        out[(size_t)NROWS*9]     = (float)(g_loss * (1.25 / ((double)NROWS * 64.0)));
        out[(size_t)NROWS*9 + 1] = (float)exp(-red[0]);
    }
}

// ======================= launch =======================
extern "C" void kernel_launch(void* const* d_in, const int* in_sizes, int n_in,
                              void* d_out, int out_size) {
    const float* x   = (const float*)d_in[0];
    const float* ew1 = (const float*)d_in[1];
    const float* eb1 = (const float*)d_in[2];
    const float* ew2 = (const float*)d_in[3];
    const float* eb2 = (const float*)d_in[4];
    const float* ew3 = (const float*)d_in[5];
    const float* eb3 = (const float*)d_in[6];
    const float* dw1 = (const float*)d_in[7];
    const float* db1 = (const float*)d_in[8];
    const float* dw2 = (const float*)d_in[9];
    const float* db2 = (const float*)d_in[10];
    const float* dw3 = (const float*)d_in[11];
    const float* db3 = (const float*)d_in[12];
    const float* cbk = (const float*)d_in[13];
    float* out = (float*)d_out;

    static_assert(E_TOTAL * 4 <= 232448, "enc smem");
    static_assert(D_TOTAL * 4 * 2 <= 232448, "dist smem x2");
    static_assert(C_TOTAL * 4 <= 232448, "dec smem");

    cudaFuncSetAttribute(vq_enc_kernel,  cudaFuncAttributeMaxDynamicSharedMemorySize, E_TOTAL * 4);
    cudaFuncSetAttribute(vq_dist_kernel, cudaFuncAttributeMaxDynamicSharedMemorySize, D_TOTAL * 4);
    cudaFuncSetAttribute(vq_dec_kernel,  cudaFuncAttributeMaxDynamicSharedMemorySize, C_TOTAL * 4);

    vq_init_kernel<<<4, 256>>>(cbk);
    vq_enc_kernel<<<152, ENT, E_TOTAL * 4>>>(x, ew1, eb1, ew2, eb2, ew3, eb3);
    vq_dist_kernel<<<304, DNT, D_TOTAL * 4>>>(cbk);
    vq_dec_kernel<<<152, CNT, C_TOTAL * 4>>>(dw1, db1, dw2, db2, dw3, db3, cbk, out);
    vq_final_kernel<<<1, 256>>>(out);
}

// round 6
// speedup vs baseline: 1.4708x; 1.0350x over previous
#include <cuda_runtime.h>
#include <math.h>

typedef unsigned long long ull;

#define NROWS 262144

// ---------------- device scratch ----------------
__device__ float  g_cnorm[1024];
__device__ int    g_counts[1024];
__device__ double g_loss;
__device__ float  g_ze[(size_t)NROWS * 64];
__device__ int    g_idx[NROWS];

// ---------------- packed f32x2 helpers ----------------
__device__ __forceinline__ void fma2(ull &d, ull a, ull b) {
    asm("fma.rn.f32x2 %0, %1, %2, %0;" : "+l"(d) : "l"(a), "l"(b));
}
__device__ __forceinline__ ull pk2(float lo, float hi) {
    ull r; asm("mov.b64 %0, {%1, %2};" : "=l"(r) : "f"(lo), "f"(hi)); return r;
}
__device__ __forceinline__ float upk_sum(ull v) {
    float lo, hi; asm("mov.b64 {%0, %1}, %2;" : "=f"(lo), "=f"(hi) : "l"(v));
    return lo + hi;
}

// ======================= init =======================
__global__ void vq_init_kernel(const float* __restrict__ cb) {
    int j = blockIdx.x * blockDim.x + threadIdx.x;
    if (j < 1024) {
        float sum = 0.f;
        #pragma unroll
        for (int k = 0; k < 64; k += 4) {
            float4 v = *reinterpret_cast<const float4*>(&cb[j*64 + k]);
            sum = fmaf(v.x,v.x, fmaf(v.y,v.y, fmaf(v.z,v.z, fmaf(v.w,v.w, sum))));
        }
        g_cnorm[j]  = sum;
        g_counts[j] = 0;
        if (j == 0) g_loss = 0.0;
    }
}

// ======================= encoder (512 threads) =======================
#define E_W2 0
#define E_B2 33280
#define E_W3 33408
#define E_B3 41856
#define E_XS 41920
#define E_H1 42240
#define E_H2 50432
#define E_TOTAL 54656
#define ENT 512

__global__ void __launch_bounds__(ENT, 1) vq_enc_kernel(
    const float* __restrict__ x,
    const float* __restrict__ w1, const float* __restrict__ b1,
    const float* __restrict__ w2, const float* __restrict__ b2,
    const float* __restrict__ w3, const float* __restrict__ b3)
{
    extern __shared__ float s[];
    const int tid = threadIdx.x;

    for (int i = tid; i < 128*256; i += ENT) { int r = i >> 8, c = i & 255; s[E_W2 + r*260 + c] = w2[i]; }
    for (int i = tid; i < 128;     i += ENT) s[E_B2 + i] = b2[i];
    for (int i = tid; i < 64*128;  i += ENT) { int r = i >> 7, c = i & 127; s[E_W3 + r*132 + c] = w3[i]; }
    for (int i = tid; i < 64;      i += ENT) s[E_B3 + i] = b3[i];

    const int col1 = tid & 255;
    const int rp0  = (tid >> 8) * 8;
    ull rw1p[9];
    const float rb1 = __ldg(&b1[col1]);
    #pragma unroll
    for (int k = 0; k < 9; k++) { float w = __ldg(&w1[col1*9 + k]); rw1p[k] = pk2(w, w); }
    __syncthreads();

    const int cp  = tid & 63, rg  = tid >> 6;
    const int cq  = tid & 31, rg3 = tid >> 5;

    for (int tile = blockIdx.x; tile < NROWS/32; tile += gridDim.x) {
        const int row0 = tile * 32;

        if (tid < 288) {
            int r = tid / 9, k = tid - r*9;
            s[E_XS + k*32 + r] = x[(size_t)(row0 + r)*9 + k];
        }
        __syncthreads();

        // L1: 9 -> 256, relu
        #pragma unroll
        for (int j = 0; j < 8; j++) {
            const int rp = rp0 + j;
            ull acc = pk2(rb1, rb1);
            #pragma unroll
            for (int k = 0; k < 9; k++)
                fma2(acc, *reinterpret_cast<const ull*>(&s[E_XS + k*32 + 2*rp]), rw1p[k]);
            float lo, hi; asm("mov.b64 {%0,%1}, %2;" : "=f"(lo), "=f"(hi) : "l"(acc));
            s[E_H1 + (2*rp)  *256 + col1] = fmaxf(lo, 0.f);
            s[E_H1 + (2*rp+1)*256 + col1] = fmaxf(hi, 0.f);
        }
        __syncthreads();

        // L2: 256 -> 128, relu (2 cols x 4 rows)
        {
            ull acc[4][2];
            const float bb0 = s[E_B2 + cp], bb1 = s[E_B2 + cp + 64];
            #pragma unroll
            for (int i = 0; i < 4; i++) { acc[i][0] = pk2(bb0, 0.f); acc[i][1] = pk2(bb1, 0.f); }
            const float* w0p = &s[E_W2 + cp*260];
            const float* w1p = &s[E_W2 + (cp+64)*260];
            const float* hp  = &s[E_H1 + rg*4*256];
            #pragma unroll 4
            for (int k4 = 0; k4 < 256; k4 += 4) {
                ulonglong2 w0  = *reinterpret_cast<const ulonglong2*>(w0p + k4);
                ulonglong2 w1v = *reinterpret_cast<const ulonglong2*>(w1p + k4);
                #pragma unroll
                for (int i = 0; i < 4; i++) {
                    ulonglong2 h = *reinterpret_cast<const ulonglong2*>(hp + i*256 + k4);
                    fma2(acc[i][0], w0.x,  h.x); fma2(acc[i][0], w0.y,  h.y);
                    fma2(acc[i][1], w1v.x, h.x); fma2(acc[i][1], w1v.y, h.y);
                }
            }
            #pragma unroll
            for (int i = 0; i < 4; i++) {
                s[E_H2 + (rg*4+i)*132 + cp]      = fmaxf(upk_sum(acc[i][0]), 0.f);
                s[E_H2 + (rg*4+i)*132 + cp + 64] = fmaxf(upk_sum(acc[i][1]), 0.f);
            }
        }
        __syncthreads();

        // L3: 128 -> 64 (2 cols x 2 rows)
        {
            ull acc[2][2];
            const float bb0 = s[E_B3 + cq], bb1 = s[E_B3 + cq + 32];
            #pragma unroll
            for (int i = 0; i < 2; i++) { acc[i][0] = pk2(bb0, 0.f); acc[i][1] = pk2(bb1, 0.f); }
            const float* w0p = &s[E_W3 + cq*132];
            const float* w1p = &s[E_W3 + (cq+32)*132];
            const float* hp  = &s[E_H2 + rg3*2*132];
            #pragma unroll 4
            for (int k4 = 0; k4 < 128; k4 += 4) {
                ulonglong2 w0  = *reinterpret_cast<const ulonglong2*>(w0p + k4);
                ulonglong2 w1v = *reinterpret_cast<const ulonglong2*>(w1p + k4);
                #pragma unroll
                for (int i = 0; i < 2; i++) {
                    ulonglong2 h = *reinterpret_cast<const ulonglong2*>(hp + i*132 + k4);
                    fma2(acc[i][0], w0.x,  h.x); fma2(acc[i][0], w0.y,  h.y);
                    fma2(acc[i][1], w1v.x, h.x); fma2(acc[i][1], w1v.y, h.y);
                }
            }
            #pragma unroll
            for (int i = 0; i < 2; i++) {
                size_t row = (size_t)(row0 + rg3*2 + i);
                g_ze[row*64 + cq]      = upk_sum(acc[i][0]);
                g_ze[row*64 + cq + 32] = upk_sum(acc[i][1]);
            }
        }
        __syncthreads();
    }
}

// ======================= distance / argmin / loss / hist =======================
#define D_ZS 0
#define D_CB 8704
#define D_SB 17664
#define D_SI 17792
#define D_ZN 17920
#define D_LR 18048
#define D_TOTAL 18056
#define DNT 256

__global__ void __launch_bounds__(DNT, 2) vq_dist_kernel(const float* __restrict__ cb)
{
    extern __shared__ float s[];
    const int tid  = threadIdx.x;
    const int lane = tid & 31, warp = tid >> 5;
    const int r0 = warp * 16;

    for (int st = blockIdx.x; st < NROWS/128; st += gridDim.x) {
        const size_t base = (size_t)st * 128 * 64;

        for (int i = tid; i < 2048; i += DNT) {
            float4 v = *reinterpret_cast<const float4*>(&g_ze[base + (size_t)i*4]);
            int r = i >> 4, c4 = (i & 15) * 4;
            *reinterpret_cast<float4*>(&s[D_ZS + r*68 + c4]) = v;
        }
        __syncthreads();

        if (tid < 128) {
            float zn = 0.f;
            const float* zp = &s[D_ZS + tid*68];
            #pragma unroll
            for (int k = 0; k < 64; k += 4) {
                float4 v = *reinterpret_cast<const float4*>(zp + k);
                zn = fmaf(v.x,v.x, fmaf(v.y,v.y, fmaf(v.z,v.z, fmaf(v.w,v.w, zn))));
            }
            s[D_ZN + tid] = zn;
        }

        // per-lane running argmin over this lane's code slice (registers, no shfl in the hot loop)
        float best[16]; int bidx[16];
        #pragma unroll
        for (int i = 0; i < 16; i++) { best[i] = 1e30f; bidx[i] = 0; }
        __syncthreads();

        for (int p = 0; p < 8; p++) {
            const int cbase = p * 128;
            for (int i = tid; i < 2048; i += DNT) {
                int r = i >> 4, q4 = (i & 15) * 4;
                ulonglong2 v = *reinterpret_cast<const ulonglong2*>(&cb[(size_t)(cbase + r)*64 + q4]);
                *reinterpret_cast<ull*>(&s[D_CB + r*70 + q4])     = v.x;
                *reinterpret_cast<ull*>(&s[D_CB + r*70 + q4 + 2]) = v.y;
            }
            if (tid < 128) s[D_CB + tid*70 + 64] = g_cnorm[cbase + tid];
            __syncthreads();

            #pragma unroll 1
            for (int cc = 0; cc < 2; cc++) {
                const int c0 = cc*64 + lane, c1 = c0 + 32;
                ull acc0[16], acc1[16];
                #pragma unroll
                for (int i = 0; i < 16; i++) { acc0[i] = 0ull; acc1[i] = 0ull; }
                const float* b0p = &s[D_CB + c0*70];
                const float* b1p = &s[D_CB + c1*70];
                const float* ap  = &s[D_ZS + r0*68];
                #pragma unroll 2
                for (int k4 = 0; k4 < 64; k4 += 4) {
                    // stride-70 rows are only 8B-aligned: must stay ull (8B) loads
                    ull b00 = *reinterpret_cast<const ull*>(b0p + k4);
                    ull b01 = *reinterpret_cast<const ull*>(b0p + k4 + 2);
                    ull b10 = *reinterpret_cast<const ull*>(b1p + k4);
                    ull b11 = *reinterpret_cast<const ull*>(b1p + k4 + 2);
                    #pragma unroll
                    for (int i = 0; i < 16; i++) {
                        ulonglong2 a = *reinterpret_cast<const ulonglong2*>(ap + i*68 + k4);
                        fma2(acc0[i], b00, a.x); fma2(acc0[i], b01, a.y);
                        fma2(acc1[i], b10, a.x); fma2(acc1[i], b11, a.y);
                    }
                }
                const float cn0 = b0p[64], cn1 = b1p[64];
                const int j0 = cbase + c0, j1 = cbase + c1;
                #pragma unroll
                for (int i = 0; i < 16; i++) {
                    float d0 = fmaf(-2.f, upk_sum(acc0[i]), cn0);
                    float d1 = fmaf(-2.f, upk_sum(acc1[i]), cn1);
                    // within-lane codes visited in increasing index order; strict < keeps lowest index
                    if (d0 < best[i]) { best[i] = d0; bidx[i] = j0; }
                    if (d1 < best[i]) { best[i] = d1; bidx[i] = j1; }
                }
            }
            __syncthreads();
        }

        // cross-lane argmin, once per tile (tie-break: smaller index)
        #pragma unroll
        for (int i = 0; i < 16; i++) {
            float v = best[i]; int id = bidx[i];
            #pragma unroll
            for (int off = 16; off; off >>= 1) {
                float ov = __shfl_down_sync(0xffffffffu, v, off);
                int   oi = __shfl_down_sync(0xffffffffu, id, off);
                if (ov < v || (ov == v && oi < id)) { v = ov; id = oi; }
            }
            if (lane == 0) {
                s[D_SB + r0 + i] = v;
                reinterpret_cast<int*>(&s[D_SI])[r0 + i] = id;
            }
        }
        __syncthreads();

        float ll = 0.f;
        if (tid < 128) {
            int id = reinterpret_cast<int*>(&s[D_SI])[tid];
            ll = s[D_SB + tid] + s[D_ZN + tid];
            g_idx[st*128 + tid] = id;
            atomicAdd(&g_counts[id], 1);
        }
        #pragma unroll
        for (int off = 16; off; off >>= 1) ll += __shfl_down_sync(0xffffffffu, ll, off);
        if (lane == 0) s[D_LR + warp] = ll;
        __syncthreads();
        if (tid == 0) {
            float tot = 0.f;
            #pragma unroll
            for (int w = 0; w < 8; w++) tot += s[D_LR + w];
            atomicAdd(&g_loss, (double)tot);
        }
        __syncthreads();
    }
}

// ======================= decoder (256 threads, C4xR8 on D2) =======================
#define C_W1  0
#define C_B1  8704
#define C_W2  8832
#define C_B2  42624
#define C_W3  42880
#define C_B3  45220
#define C_S1  45232
#define C_S2  53552
#define C_IDX 57776
#define C_TOTAL 57808
#define CNT 256

__global__ void __launch_bounds__(CNT, 1) vq_dec_kernel(
    const float* __restrict__ w1, const float* __restrict__ b1,
    const float* __restrict__ w2, const float* __restrict__ b2,
    const float* __restrict__ w3, const float* __restrict__ b3,
    const float* __restrict__ cb, float* __restrict__ out)
{
    extern __shared__ float s[];
    const int tid = threadIdx.x;

    for (int i = tid; i < 128*64;  i += CNT) { int r = i >> 6, c = i & 63;  s[C_W1 + r*68  + c] = w1[i]; }
    for (int i = tid; i < 128;     i += CNT) s[C_B1 + i] = b1[i];
    for (int i = tid; i < 256*128; i += CNT) { int r = i >> 7, c = i & 127; s[C_W2 + r*132 + c] = w2[i]; }
    for (int i = tid; i < 256;     i += CNT) s[C_B2 + i] = b2[i];
    for (int i = tid; i < 9*256;   i += CNT) { int r = i >> 8, c = i & 255; s[C_W3 + r*260 + c] = w3[i]; }
    for (int i = tid; i < 9;       i += CNT) s[C_B3 + i] = b3[i];
    __syncthreads();

    const int cp = tid & 63, rg = tid >> 6;   // D1: cols (cp, cp+64), rows rg*8..+7
                                              // D2: cols cp+{0,64,128,192}, rows rg*8..+7
    int* sidx = reinterpret_cast<int*>(&s[C_IDX]);

    for (int tile = blockIdx.x; tile < NROWS/32; tile += gridDim.x) {
        const int row0 = tile * 32;
        if (tid < 32) sidx[tid] = g_idx[row0 + tid];
        __syncthreads();

        // gather quantized rows from codebook (L2-resident): 2 float4 per thread
        #pragma unroll
        for (int t = tid; t < 512; t += CNT) {
            int r = t >> 4, j = (t & 15) * 4;
            float4 v = *reinterpret_cast<const float4*>(&cb[(size_t)sidx[r]*64 + j]);
            *reinterpret_cast<float4*>(&s[C_S1 + r*68 + j]) = v;
        }
        __syncthreads();

        // D1: 64 -> 128, relu (2 cols x 8 rows)
        {
            ull acc[8][2];
            const float bb0 = s[C_B1 + cp], bb1 = s[C_B1 + cp + 64];
            #pragma unroll
            for (int i = 0; i < 8; i++) { acc[i][0] = pk2(bb0, 0.f); acc[i][1] = pk2(bb1, 0.f); }
            const float* w0p = &s[C_W1 + cp*68];
            const float* w1p = &s[C_W1 + (cp+64)*68];
            const float* hp  = &s[C_S1 + rg*8*68];
            #pragma unroll 4
            for (int k4 = 0; k4 < 64; k4 += 4) {
                ulonglong2 w0  = *reinterpret_cast<const ulonglong2*>(w0p + k4);
                ulonglong2 w1v = *reinterpret_cast<const ulonglong2*>(w1p + k4);
                #pragma unroll
                for (int i = 0; i < 8; i++) {
                    ulonglong2 h = *reinterpret_cast<const ulonglong2*>(hp + i*68 + k4);
                    fma2(acc[i][0], w0.x,  h.x); fma2(acc[i][0], w0.y,  h.y);
                    fma2(acc[i][1], w1v.x, h.x); fma2(acc[i][1], w1v.y, h.y);
                }
            }
            #pragma unroll
            for (int i = 0; i < 8; i++) {
                s[C_S2 + (rg*8+i)*132 + cp]      = fmaxf(upk_sum(acc[i][0]), 0.f);
                s[C_S2 + (rg*8+i)*132 + cp + 64] = fmaxf(upk_sum(acc[i][1]), 0.f);
            }
        }
        __syncthreads();

        // D2: 128 -> 256, relu (4 cols x 8 rows)
        {
            ull acc[8][4];
            #pragma unroll
            for (int c = 0; c < 4; c++) {
                const float bb = s[C_B2 + cp + 64*c];
                #pragma unroll
                for (int i = 0; i < 8; i++) acc[i][c] = pk2(bb, 0.f);
            }
            const float* wp0 = &s[C_W2 + cp*132];
            const float* wp1 = &s[C_W2 + (cp+64)*132];
            const float* wp2 = &s[C_W2 + (cp+128)*132];
            const float* wp3 = &s[C_W2 + (cp+192)*132];
            const float* hp  = &s[C_S2 + rg*8*132];
            #pragma unroll 2
            for (int k4 = 0; k4 < 128; k4 += 4) {
                ulonglong2 w0 = *reinterpret_cast<const ulonglong2*>(wp0 + k4);
                ulonglong2 w1 = *reinterpret_cast<const ulonglong2*>(wp1 + k4);
                ulonglong2 w2 = *reinterpret_cast<const ulonglong2*>(wp2 + k4);
                ulonglong2 w3 = *reinterpret_cast<const ulonglong2*>(wp3 + k4);
                #pragma unroll
                for (int i = 0; i < 8; i++) {
                    ulonglong2 h = *reinterpret_cast<const ulonglong2*>(hp + i*132 + k4);
                    fma2(acc[i][0], w0.x, h.x); fma2(acc[i][0], w0.y, h.y);
                    fma2(acc[i][1], w1.x, h.x); fma2(acc[i][1], w1.y, h.y);
                    fma2(acc[i][2], w2.x, h.x); fma2(acc[i][2], w2.y, h.y);
                    fma2(acc[i][3], w3.x, h.x); fma2(acc[i][3], w3.y, h.y);
                }
            }
            #pragma unroll
            for (int i = 0; i < 8; i++)
                #pragma unroll
                for (int c = 0; c < 4; c++)
                    s[C_S1 + (rg*8+i)*260 + cp + 64*c] = fmaxf(upk_sum(acc[i][c]), 0.f);
        }
        __syncthreads();

        // D3: 256 -> 9
        for (int t = tid; t < 288; t += CNT) {
            int r = t / 9, c = t - r*9;
            ull a0 = pk2(s[C_B3 + c], 0.f), a1 = 0ull;
            const float* wp  = &s[C_W3 + c*260];
            const float* hp2 = &s[C_S1 + r*260];
            #pragma unroll 4
            for (int k4 = 0; k4 < 256; k4 += 4) {
                ulonglong2 w = *reinterpret_cast<const ulonglong2*>(wp + k4);
                ulonglong2 h = *reinterpret_cast<const ulonglong2*>(hp2 + k4);
                fma2(a0, w.x, h.x); fma2(a1, w.y, h.y);
            }
            out[(size_t)(row0 + r)*9 + c] = upk_sum(a0) + upk_sum(a1);
        }
        __syncthreads();
    }
}

// ======================= finalize =======================
__global__ void vq_final_kernel(float* __restrict__ out) {
    __shared__ double red[256];
    const int tid = threadIdx.x;
    double ent = 0.0;
    for (int j = tid; j < 1024; j += 256) {
        double p = (double)g_counts[j] / (double)NROWS;
        ent += p * log(p + 1e-10);
    }
    red[tid] = ent;
    __syncthreads();
    for (int off = 128; off; off >>= 1) {
        if (tid < off) red[tid] += red[tid + off];
        __syncthreads();
    }
    if (tid == 0) {
        out[(size_t)NROWS*9]     = (float)(g_loss * (1.25 / ((double)NROWS * 64.0)));
        out[(size_t)NROWS*9 + 1] = (float)exp(-red[0]);
    }
}

// ======================= launch =======================
extern "C" void kernel_launch(void* const* d_in, const int* in_sizes, int n_in,
                              void* d_out, int out_size) {
    const float* x   = (const float*)d_in[0];
    const float* ew1 = (const float*)d_in[1];
    const float* eb1 = (const float*)d_in[2];
    const float* ew2 = (const float*)d_in[3];
    const float* eb2 = (const float*)d_in[4];
    const float* ew3 = (const float*)d_in[5];
    const float* eb3 = (const float*)d_in[6];
    const float* dw1 = (const float*)d_in[7];
    const float* db1 = (const float*)d_in[8];
    const float* dw2 = (const float*)d_in[9];
    const float* db2 = (const float*)d_in[10];
    const float* dw3 = (const float*)d_in[11];
    const float* db3 = (const float*)d_in[12];
    const float* cbk = (const float*)d_in[13];
    float* out = (float*)d_out;

    static_assert(E_TOTAL * 4 <= 232448, "enc smem");
    static_assert(D_TOTAL * 4 * 2 <= 232448, "dist smem x2");
    static_assert(C_TOTAL * 4 <= 232448, "dec smem");

    cudaFuncSetAttribute(vq_enc_kernel,  cudaFuncAttributeMaxDynamicSharedMemorySize, E_TOTAL * 4);
    cudaFuncSetAttribute(vq_dist_kernel, cudaFuncAttributeMaxDynamicSharedMemorySize, D_TOTAL * 4);
    cudaFuncSetAttribute(vq_dec_kernel,  cudaFuncAttributeMaxDynamicSharedMemorySize, C_TOTAL * 4);

    vq_init_kernel<<<4, 256>>>(cbk);
    vq_enc_kernel<<<152, ENT, E_TOTAL * 4>>>(x, ew1, eb1, ew2, eb2, ew3, eb3);
    vq_dist_kernel<<<304, DNT, D_TOTAL * 4>>>(cbk);
    vq_dec_kernel<<<152, CNT, C_TOTAL * 4>>>(dw1, db1, dw2, db2, dw3, db3, cbk, out);
    vq_final_kernel<<<1, 256>>>(out);
}

// round 7
// speedup vs baseline: 2.0089x; 1.3659x over previous
#include <cuda_runtime.h>
#include <math.h>

typedef unsigned long long ull;

#define NROWS 262144

// ---------------- device scratch ----------------
__device__ float  g_cnorm[1024];
__device__ int    g_counts[1024];
__device__ double g_loss;
__device__ float  g_ze[(size_t)NROWS * 64];
__device__ int    g_idx[NROWS];
__device__ float  g_table[1024 * 9];

// ---------------- packed f32x2 helpers ----------------
__device__ __forceinline__ void fma2(ull &d, ull a, ull b) {
    asm("fma.rn.f32x2 %0, %1, %2, %0;" : "+l"(d) : "l"(a), "l"(b));
}
__device__ __forceinline__ ull pk2(float lo, float hi) {
    ull r; asm("mov.b64 %0, {%1, %2};" : "=l"(r) : "f"(lo), "f"(hi)); return r;
}
__device__ __forceinline__ float upk_sum(ull v) {
    float lo, hi; asm("mov.b64 {%0, %1}, %2;" : "=f"(lo), "=f"(hi) : "l"(v));
    return lo + hi;
}

// ======================= init =======================
__global__ void vq_init_kernel(const float* __restrict__ cb) {
    int j = blockIdx.x * blockDim.x + threadIdx.x;
    if (j < 1024) {
        float sum = 0.f;
        #pragma unroll
        for (int k = 0; k < 64; k += 4) {
            float4 v = *reinterpret_cast<const float4*>(&cb[j*64 + k]);
            sum = fmaf(v.x,v.x, fmaf(v.y,v.y, fmaf(v.z,v.z, fmaf(v.w,v.w, sum))));
        }
        g_cnorm[j]  = sum;
        g_counts[j] = 0;
        if (j == 0) g_loss = 0.0;
    }
}

// ======================= encoder (512 threads) =======================
#define E_W2 0
#define E_B2 33280
#define E_W3 33408
#define E_B3 41856
#define E_XS 41920
#define E_H1 42240
#define E_H2 50432
#define E_TOTAL 54656
#define ENT 512

__global__ void __launch_bounds__(ENT, 1) vq_enc_kernel(
    const float* __restrict__ x,
    const float* __restrict__ w1, const float* __restrict__ b1,
    const float* __restrict__ w2, const float* __restrict__ b2,
    const float* __restrict__ w3, const float* __restrict__ b3)
{
    extern __shared__ float s[];
    const int tid = threadIdx.x;

    for (int i = tid; i < 128*256; i += ENT) { int r = i >> 8, c = i & 255; s[E_W2 + r*260 + c] = w2[i]; }
    for (int i = tid; i < 128;     i += ENT) s[E_B2 + i] = b2[i];
    for (int i = tid; i < 64*128;  i += ENT) { int r = i >> 7, c = i & 127; s[E_W3 + r*132 + c] = w3[i]; }
    for (int i = tid; i < 64;      i += ENT) s[E_B3 + i] = b3[i];

    const int col1 = tid & 255;
    const int rp0  = (tid >> 8) * 8;
    ull rw1p[9];
    const float rb1 = __ldg(&b1[col1]);
    #pragma unroll
    for (int k = 0; k < 9; k++) { float w = __ldg(&w1[col1*9 + k]); rw1p[k] = pk2(w, w); }
    __syncthreads();

    const int cp  = tid & 63, rg  = tid >> 6;
    const int cq  = tid & 31, rg3 = tid >> 5;

    for (int tile = blockIdx.x; tile < NROWS/32; tile += gridDim.x) {
        const int row0 = tile * 32;

        if (tid < 288) {
            int r = tid / 9, k = tid - r*9;
            s[E_XS + k*32 + r] = x[(size_t)(row0 + r)*9 + k];
        }
        __syncthreads();

        // L1: 9 -> 256, relu
        #pragma unroll
        for (int j = 0; j < 8; j++) {
            const int rp = rp0 + j;
            ull acc = pk2(rb1, rb1);
            #pragma unroll
            for (int k = 0; k < 9; k++)
                fma2(acc, *reinterpret_cast<const ull*>(&s[E_XS + k*32 + 2*rp]), rw1p[k]);
            float lo, hi; asm("mov.b64 {%0,%1}, %2;" : "=f"(lo), "=f"(hi) : "l"(acc));
            s[E_H1 + (2*rp)  *256 + col1] = fmaxf(lo, 0.f);
            s[E_H1 + (2*rp+1)*256 + col1] = fmaxf(hi, 0.f);
        }
        __syncthreads();

        // L2: 256 -> 128, relu (2 cols x 4 rows)
        {
            ull acc[4][2];
            const float bb0 = s[E_B2 + cp], bb1 = s[E_B2 + cp + 64];
            #pragma unroll
            for (int i = 0; i < 4; i++) { acc[i][0] = pk2(bb0, 0.f); acc[i][1] = pk2(bb1, 0.f); }
            const float* w0p = &s[E_W2 + cp*260];
            const float* w1p = &s[E_W2 + (cp+64)*260];
            const float* hp  = &s[E_H1 + rg*4*256];
            #pragma unroll 4
            for (int k4 = 0; k4 < 256; k4 += 4) {
                ulonglong2 w0  = *reinterpret_cast<const ulonglong2*>(w0p + k4);
                ulonglong2 w1v = *reinterpret_cast<const ulonglong2*>(w1p + k4);
                #pragma unroll
                for (int i = 0; i < 4; i++) {
                    ulonglong2 h = *reinterpret_cast<const ulonglong2*>(hp + i*256 + k4);
                    fma2(acc[i][0], w0.x,  h.x); fma2(acc[i][0], w0.y,  h.y);
                    fma2(acc[i][1], w1v.x, h.x); fma2(acc[i][1], w1v.y, h.y);
                }
            }
            #pragma unroll
            for (int i = 0; i < 4; i++) {
                s[E_H2 + (rg*4+i)*132 + cp]      = fmaxf(upk_sum(acc[i][0]), 0.f);
                s[E_H2 + (rg*4+i)*132 + cp + 64] = fmaxf(upk_sum(acc[i][1]), 0.f);
            }
        }
        __syncthreads();

        // L3: 128 -> 64 (2 cols x 2 rows)
        {
            ull acc[2][2];
            const float bb0 = s[E_B3 + cq], bb1 = s[E_B3 + cq + 32];
            #pragma unroll
            for (int i = 0; i < 2; i++) { acc[i][0] = pk2(bb0, 0.f); acc[i][1] = pk2(bb1, 0.f); }
            const float* w0p = &s[E_W3 + cq*132];
            const float* w1p = &s[E_W3 + (cq+32)*132];
            const float* hp  = &s[E_H2 + rg3*2*132];
            #pragma unroll 4
            for (int k4 = 0; k4 < 128; k4 += 4) {
                ulonglong2 w0  = *reinterpret_cast<const ulonglong2*>(w0p + k4);
                ulonglong2 w1v = *reinterpret_cast<const ulonglong2*>(w1p + k4);
                #pragma unroll
                for (int i = 0; i < 2; i++) {
                    ulonglong2 h = *reinterpret_cast<const ulonglong2*>(hp + i*132 + k4);
                    fma2(acc[i][0], w0.x,  h.x); fma2(acc[i][0], w0.y,  h.y);
                    fma2(acc[i][1], w1v.x, h.x); fma2(acc[i][1], w1v.y, h.y);
                }
            }
            #pragma unroll
            for (int i = 0; i < 2; i++) {
                size_t row = (size_t)(row0 + rg3*2 + i);
                g_ze[row*64 + cq]      = upk_sum(acc[i][0]);
                g_ze[row*64 + cq + 32] = upk_sum(acc[i][1]);
            }
        }
        __syncthreads();
    }
}

// ======================= distance / argmin / loss / hist =======================
#define D_ZS 0
#define D_CB 8704
#define D_SB 17664
#define D_SI 17792
#define D_ZN 17920
#define D_LR 18048
#define D_TOTAL 18056
#define DNT 256

__global__ void __launch_bounds__(DNT, 2) vq_dist_kernel(const float* __restrict__ cb)
{
    extern __shared__ float s[];
    const int tid  = threadIdx.x;
    const int lane = tid & 31, warp = tid >> 5;
    const int r0 = warp * 16;

    for (int st = blockIdx.x; st < NROWS/128; st += gridDim.x) {
        const size_t base = (size_t)st * 128 * 64;

        for (int i = tid; i < 2048; i += DNT) {
            float4 v = *reinterpret_cast<const float4*>(&g_ze[base + (size_t)i*4]);
            int r = i >> 4, c4 = (i & 15) * 4;
            *reinterpret_cast<float4*>(&s[D_ZS + r*68 + c4]) = v;
        }
        __syncthreads();

        if (tid < 128) {
            float zn = 0.f;
            const float* zp = &s[D_ZS + tid*68];
            #pragma unroll
            for (int k = 0; k < 64; k += 4) {
                float4 v = *reinterpret_cast<const float4*>(zp + k);
                zn = fmaf(v.x,v.x, fmaf(v.y,v.y, fmaf(v.z,v.z, fmaf(v.w,v.w, zn))));
            }
            s[D_ZN + tid] = zn;
        }

        float best[16]; int bidx[16];
        #pragma unroll
        for (int i = 0; i < 16; i++) { best[i] = 1e30f; bidx[i] = 0; }
        __syncthreads();

        for (int p = 0; p < 8; p++) {
            const int cbase = p * 128;
            for (int i = tid; i < 2048; i += DNT) {
                int r = i >> 4, q4 = (i & 15) * 4;
                ulonglong2 v = *reinterpret_cast<const ulonglong2*>(&cb[(size_t)(cbase + r)*64 + q4]);
                *reinterpret_cast<ull*>(&s[D_CB + r*70 + q4])     = v.x;
                *reinterpret_cast<ull*>(&s[D_CB + r*70 + q4 + 2]) = v.y;
            }
            if (tid < 128) s[D_CB + tid*70 + 64] = g_cnorm[cbase + tid];
            __syncthreads();

            #pragma unroll 1
            for (int cc = 0; cc < 2; cc++) {
                const int c0 = cc*64 + lane, c1 = c0 + 32;
                ull acc0[16], acc1[16];
                #pragma unroll
                for (int i = 0; i < 16; i++) { acc0[i] = 0ull; acc1[i] = 0ull; }
                const float* b0p = &s[D_CB + c0*70];
                const float* b1p = &s[D_CB + c1*70];
                const float* ap  = &s[D_ZS + r0*68];
                #pragma unroll 2
                for (int k4 = 0; k4 < 64; k4 += 4) {
                    // stride-70 rows are only 8B-aligned: must stay ull (8B) loads
                    ull b00 = *reinterpret_cast<const ull*>(b0p + k4);
                    ull b01 = *reinterpret_cast<const ull*>(b0p + k4 + 2);
                    ull b10 = *reinterpret_cast<const ull*>(b1p + k4);
                    ull b11 = *reinterpret_cast<const ull*>(b1p + k4 + 2);
                    #pragma unroll
                    for (int i = 0; i < 16; i++) {
                        ulonglong2 a = *reinterpret_cast<const ulonglong2*>(ap + i*68 + k4);
                        fma2(acc0[i], b00, a.x); fma2(acc0[i], b01, a.y);
                        fma2(acc1[i], b10, a.x); fma2(acc1[i], b11, a.y);
                    }
                }
                const float cn0 = b0p[64], cn1 = b1p[64];
                const int j0 = cbase + c0, j1 = cbase + c1;
                #pragma unroll
                for (int i = 0; i < 16; i++) {
                    float d0 = fmaf(-2.f, upk_sum(acc0[i]), cn0);
                    float d1 = fmaf(-2.f, upk_sum(acc1[i]), cn1);
                    if (d0 < best[i]) { best[i] = d0; bidx[i] = j0; }
                    if (d1 < best[i]) { best[i] = d1; bidx[i] = j1; }
                }
            }
            __syncthreads();
        }

        // cross-lane argmin, once per tile (tie-break: smaller index)
        #pragma unroll
        for (int i = 0; i < 16; i++) {
            float v = best[i]; int id = bidx[i];
            #pragma unroll
            for (int off = 16; off; off >>= 1) {
                float ov = __shfl_down_sync(0xffffffffu, v, off);
                int   oi = __shfl_down_sync(0xffffffffu, id, off);
                if (ov < v || (ov == v && oi < id)) { v = ov; id = oi; }
            }
            if (lane == 0) {
                s[D_SB + r0 + i] = v;
                reinterpret_cast<int*>(&s[D_SI])[r0 + i] = id;
            }
        }
        __syncthreads();

        float ll = 0.f;
        if (tid < 128) {
            int id = reinterpret_cast<int*>(&s[D_SI])[tid];
            ll = s[D_SB + tid] + s[D_ZN + tid];
            g_idx[st*128 + tid] = id;
            atomicAdd(&g_counts[id], 1);
        }
        #pragma unroll
        for (int off = 16; off; off >>= 1) ll += __shfl_down_sync(0xffffffffu, ll, off);
        if (lane == 0) s[D_LR + warp] = ll;
        __syncthreads();
        if (tid == 0) {
            float tot = 0.f;
            #pragma unroll
            for (int w = 0; w < 8; w++) tot += s[D_LR + w];
            atomicAdd(&g_loss, (double)tot);
        }
        __syncthreads();
    }
}

// ======================= decoder table: mlp3 over the 1024 codebook rows =======================
#define C_W1  0
#define C_B1  8704
#define C_W2  8832
#define C_B2  42624
#define C_W3  42880
#define C_B3  45220
#define C_S1  45232
#define C_S2  53552
#define C_TOTAL 57808
#define CNT 256

__global__ void __launch_bounds__(CNT, 1) vq_dectab_kernel(
    const float* __restrict__ w1, const float* __restrict__ b1,
    const float* __restrict__ w2, const float* __restrict__ b2,
    const float* __restrict__ w3, const float* __restrict__ b3,
    const float* __restrict__ cb)
{
    extern __shared__ float s[];
    const int tid = threadIdx.x;

    for (int i = tid; i < 128*64;  i += CNT) { int r = i >> 6, c = i & 63;  s[C_W1 + r*68  + c] = w1[i]; }
    for (int i = tid; i < 128;     i += CNT) s[C_B1 + i] = b1[i];
    for (int i = tid; i < 256*128; i += CNT) { int r = i >> 7, c = i & 127; s[C_W2 + r*132 + c] = w2[i]; }
    for (int i = tid; i < 256;     i += CNT) s[C_B2 + i] = b2[i];
    for (int i = tid; i < 9*256;   i += CNT) { int r = i >> 8, c = i & 255; s[C_W3 + r*260 + c] = w3[i]; }
    for (int i = tid; i < 9;       i += CNT) s[C_B3 + i] = b3[i];
    __syncthreads();

    const int cp = tid & 63, rg = tid >> 6;

    for (int tile = blockIdx.x; tile < 1024/32; tile += gridDim.x) {
        const int row0 = tile * 32;

        // stage 32 codebook rows
        for (int t = tid; t < 512; t += CNT) {
            int r = t >> 4, j = (t & 15) * 4;
            float4 v = *reinterpret_cast<const float4*>(&cb[(size_t)(row0 + r)*64 + j]);
            *reinterpret_cast<float4*>(&s[C_S1 + r*68 + j]) = v;
        }
        __syncthreads();

        // D1: 64 -> 128, relu (2 cols x 8 rows)
        {
            ull acc[8][2];
            const float bb0 = s[C_B1 + cp], bb1 = s[C_B1 + cp + 64];
            #pragma unroll
            for (int i = 0; i < 8; i++) { acc[i][0] = pk2(bb0, 0.f); acc[i][1] = pk2(bb1, 0.f); }
            const float* w0p = &s[C_W1 + cp*68];
            const float* w1p = &s[C_W1 + (cp+64)*68];
            const float* hp  = &s[C_S1 + rg*8*68];
            #pragma unroll 4
            for (int k4 = 0; k4 < 64; k4 += 4) {
                ulonglong2 w0  = *reinterpret_cast<const ulonglong2*>(w0p + k4);
                ulonglong2 w1v = *reinterpret_cast<const ulonglong2*>(w1p + k4);
                #pragma unroll
                for (int i = 0; i < 8; i++) {
                    ulonglong2 h = *reinterpret_cast<const ulonglong2*>(hp + i*68 + k4);
                    fma2(acc[i][0], w0.x,  h.x); fma2(acc[i][0], w0.y,  h.y);
                    fma2(acc[i][1], w1v.x, h.x); fma2(acc[i][1], w1v.y, h.y);
                }
            }
            #pragma unroll
            for (int i = 0; i < 8; i++) {
                s[C_S2 + (rg*8+i)*132 + cp]      = fmaxf(upk_sum(acc[i][0]), 0.f);
                s[C_S2 + (rg*8+i)*132 + cp + 64] = fmaxf(upk_sum(acc[i][1]), 0.f);
            }
        }
        __syncthreads();

        // D2: 128 -> 256, relu (4 cols x 8 rows)
        {
            ull acc[8][4];
            #pragma unroll
            for (int c = 0; c < 4; c++) {
                const float bb = s[C_B2 + cp + 64*c];
                #pragma unroll
                for (int i = 0; i < 8; i++) acc[i][c] = pk2(bb, 0.f);
            }
            const float* wp0 = &s[C_W2 + cp*132];
            const float* wp1 = &s[C_W2 + (cp+64)*132];
            const float* wp2 = &s[C_W2 + (cp+128)*132];
            const float* wp3 = &s[C_W2 + (cp+192)*132];
            const float* hp  = &s[C_S2 + rg*8*132];
            #pragma unroll 2
            for (int k4 = 0; k4 < 128; k4 += 4) {
                ulonglong2 w0 = *reinterpret_cast<const ulonglong2*>(wp0 + k4);
                ulonglong2 w1 = *reinterpret_cast<const ulonglong2*>(wp1 + k4);
                ulonglong2 w2 = *reinterpret_cast<const ulonglong2*>(wp2 + k4);
                ulonglong2 w3 = *reinterpret_cast<const ulonglong2*>(wp3 + k4);
                #pragma unroll
                for (int i = 0; i < 8; i++) {
                    ulonglong2 h = *reinterpret_cast<const ulonglong2*>(hp + i*132 + k4);
                    fma2(acc[i][0], w0.x, h.x); fma2(acc[i][0], w0.y, h.y);
                    fma2(acc[i][1], w1.x, h.x); fma2(acc[i][1], w1.y, h.y);
                    fma2(acc[i][2], w2.x, h.x); fma2(acc[i][2], w2.y, h.y);
                    fma2(acc[i][3], w3.x, h.x); fma2(acc[i][3], w3.y, h.y);
                }
            }
            #pragma unroll
            for (int i = 0; i < 8; i++)
                #pragma unroll
                for (int c = 0; c < 4; c++)
                    s[C_S1 + (rg*8+i)*260 + cp + 64*c] = fmaxf(upk_sum(acc[i][c]), 0.f);
        }
        __syncthreads();

        // D3: 256 -> 9, to table
        for (int t = tid; t < 288; t += CNT) {
            int r = t / 9, c = t - r*9;
            ull a0 = pk2(s[C_B3 + c], 0.f), a1 = 0ull;
            const float* wp  = &s[C_W3 + c*260];
            const float* hp2 = &s[C_S1 + r*260];
            #pragma unroll 4
            for (int k4 = 0; k4 < 256; k4 += 4) {
                ulonglong2 w = *reinterpret_cast<const ulonglong2*>(wp + k4);
                ulonglong2 h = *reinterpret_cast<const ulonglong2*>(hp2 + k4);
                fma2(a0, w.x, h.x); fma2(a1, w.y, h.y);
            }
            g_table[(row0 + r)*9 + c] = upk_sum(a0) + upk_sum(a1);
        }
        __syncthreads();
    }
}

// ======================= gather: out[i] = table[idx[i]] =======================
__global__ void vq_gather_kernel(float* __restrict__ out) {
    const int e = blockIdx.x * blockDim.x + threadIdx.x;   // over NROWS*9
    if (e < NROWS * 9) {
        const unsigned row = (unsigned)e / 9u;
        const unsigned c   = (unsigned)e - row * 9u;
        out[e] = g_table[g_idx[row] * 9 + c];
    }
}

// ======================= finalize =======================
__global__ void vq_final_kernel(float* __restrict__ out) {
    __shared__ double red[256];
    const int tid = threadIdx.x;
    double ent = 0.0;
    for (int j = tid; j < 1024; j += 256) {
        double p = (double)g_counts[j] / (double)NROWS;
        ent += p * log(p + 1e-10);
    }
    red[tid] = ent;
    __syncthreads();
    for (int off = 128; off; off >>= 1) {
        if (tid < off) red[tid] += red[tid + off];
        __syncthreads();
    }
    if (tid == 0) {
        out[(size_t)NROWS*9]     = (float)(g_loss * (1.25 / ((double)NROWS * 64.0)));
        out[(size_t)NROWS*9 + 1] = (float)exp(-red[0]);
    }
}

// ======================= launch =======================
extern "C" void kernel_launch(void* const* d_in, const int* in_sizes, int n_in,
                              void* d_out, int out_size) {
    const float* x   = (const float*)d_in[0];
    const float* ew1 = (const float*)d_in[1];
    const float* eb1 = (const float*)d_in[2];
    const float* ew2 = (const float*)d_in[3];
    const float* eb2 = (const float*)d_in[4];
    const float* ew3 = (const float*)d_in[5];
    const float* eb3 = (const float*)d_in[6];
    const float* dw1 = (const float*)d_in[7];
    const float* db1 = (const float*)d_in[8];
    const float* dw2 = (const float*)d_in[9];
    const float* db2 = (const float*)d_in[10];
    const float* dw3 = (const float*)d_in[11];
    const float* db3 = (const float*)d_in[12];
    const float* cbk = (const float*)d_in[13];
    float* out = (float*)d_out;

    static_assert(E_TOTAL * 4 <= 232448, "enc smem");
    static_assert(D_TOTAL * 4 * 2 <= 232448, "dist smem x2");
    static_assert(C_TOTAL * 4 <= 232448, "dectab smem");

    cudaFuncSetAttribute(vq_enc_kernel,    cudaFuncAttributeMaxDynamicSharedMemorySize, E_TOTAL * 4);
    cudaFuncSetAttribute(vq_dist_kernel,   cudaFuncAttributeMaxDynamicSharedMemorySize, D_TOTAL * 4);
    cudaFuncSetAttribute(vq_dectab_kernel, cudaFuncAttributeMaxDynamicSharedMemorySize, C_TOTAL * 4);

    vq_init_kernel<<<4, 256>>>(cbk);
    vq_enc_kernel<<<152, ENT, E_TOTAL * 4>>>(x, ew1, eb1, ew2, eb2, ew3, eb3);
    vq_dist_kernel<<<304, DNT, D_TOTAL * 4>>>(cbk);
    vq_dectab_kernel<<<32, CNT, C_TOTAL * 4>>>(dw1, db1, dw2, db2, dw3, db3, cbk);
    vq_gather_kernel<<<(NROWS*9 + 255)/256, 256>>>(out);
    vq_final_kernel<<<1, 256>>>(out);
}